// round 7
// baseline (speedup 1.0000x reference)
#include <cuda_runtime.h>
#include <cuda_fp16.h>
#include <math.h>
#include <stdint.h>

#define BB 2
#define SS 2048
#define DD 1024
#define HH 16
#define DK 64
#define MTOT (BB*SS)

#define SCALE 12.5f                  // 100/sqrt(64)
#define INV_HS (1.0f/32768.0f)       // 1/(H*S)

// ---------------- scratch (static device globals; no allocation) -------------
__device__ float g_Q[MTOT*DD];
__device__ float g_K[MTOT*DD];
__device__ float g_V[MTOT*DD];
__device__ float g_C[MTOT*DD];
// score scratch: 512 blocks x 32 tiles x 256 threads x 32 floats = 512MB
__device__ float g_S[512ull * 32 * 256 * 32];

// ---------------- helpers -----------------------------------------------------
__device__ __forceinline__ void split_h2(float a, float b, __half2& h, __half2& l) {
    h = __floats2half2_rn(a, b);
    float2 f = __half22float2(h);
    l = __floats2half2_rn(a - f.x, b - f.y);
}

__device__ __forceinline__ void mma_f16(float c[4],
                                        uint32_t a0, uint32_t a1, uint32_t a2, uint32_t a3,
                                        uint32_t b0, uint32_t b1) {
    asm volatile(
        "mma.sync.aligned.m16n8k16.row.col.f32.f16.f16.f32 "
        "{%0,%1,%2,%3}, {%4,%5,%6,%7}, {%8,%9}, {%0,%1,%2,%3};"
        : "+f"(c[0]), "+f"(c[1]), "+f"(c[2]), "+f"(c[3])
        : "r"(a0), "r"(a1), "r"(a2), "r"(a3), "r"(b0), "r"(b1));
}

#define U32AT(p) (*(const uint32_t*)(p))

// ---------------- zero mean_atp region ---------------------------------------
__global__ void zero_atp_kernel(float* __restrict__ atp) {
    int i = blockIdx.x * blockDim.x + threadIdx.x;
    if (i < BB*SS) atp[i] = 0.0f;
}

// ---------------- 3xFP16 mma.sync GEMM: Y[M,1024] = X @ W^T + b ---------------
// BM=BN=128, BK=32, 256 threads (8 warps 2x4), warp tile 64x32, m16n8k16.
// Register-prefetch: stage s+1 LDGs issued before stage-s MMA block.
#define GK 1024
#define GN 1024
#define LDH 40                         // halfs per smem row (32 + 8 pad)
#define GEMM_SMEM 40960                // XsH,XsL,WsH,WsL: 4 * 128*40*2 bytes

__global__ __launch_bounds__(256, 2) void gemm_h(
    const float* __restrict__ X, const float* __restrict__ W,
    const float* __restrict__ bias, float* __restrict__ Y)
{
    extern __shared__ char sm[];
    __half* XsH = (__half*)sm;                     // [128][40]
    __half* XsL = (__half*)(sm + 10240);
    __half* WsH = (__half*)(sm + 20480);
    __half* WsL = (__half*)(sm + 30720);

    const int t = threadIdx.x;
    const int w = t >> 5;
    const int lane = t & 31;
    const int g = lane >> 2;
    const int tig = lane & 3;
    const int warp_m = (w >> 2) * 64;
    const int warp_n = (w & 3) * 32;
    const int bm = blockIdx.y * 128;
    const int bn = blockIdx.x * 128;

    const int lrow = t >> 3;              // 0..31
    const int lcol = (t & 7) * 4;         // 0..28

    float acc[4][4][4];
#pragma unroll
    for (int mi = 0; mi < 4; ++mi)
#pragma unroll
        for (int ni = 0; ni < 4; ++ni)
#pragma unroll
            for (int j = 0; j < 4; ++j) acc[mi][ni][j] = 0.0f;

    const float* Xg = X + (size_t)(bm + lrow) * GK + lcol;
    const float* Wg = W + (size_t)(bn + lrow) * GK + lcol;

    float4 xr[4], wr[4];
#pragma unroll
    for (int ir = 0; ir < 4; ++ir) {
        xr[ir] = *(const float4*)(Xg + (size_t)(32 * ir) * GK);
        wr[ir] = *(const float4*)(Wg + (size_t)(32 * ir) * GK);
    }

    for (int s = 0; s < GK / 32; ++s) {
        __syncthreads();
#pragma unroll
        for (int ir = 0; ir < 4; ++ir) {
            const int row = lrow + 32 * ir;
            __half2 h01, l01, h23, l23;
            split_h2(xr[ir].x, xr[ir].y, h01, l01);
            split_h2(xr[ir].z, xr[ir].w, h23, l23);
            *(__half2*)&XsH[row * LDH + lcol]     = h01;
            *(__half2*)&XsH[row * LDH + lcol + 2] = h23;
            *(__half2*)&XsL[row * LDH + lcol]     = l01;
            *(__half2*)&XsL[row * LDH + lcol + 2] = l23;
            split_h2(wr[ir].x, wr[ir].y, h01, l01);
            split_h2(wr[ir].z, wr[ir].w, h23, l23);
            *(__half2*)&WsH[row * LDH + lcol]     = h01;
            *(__half2*)&WsH[row * LDH + lcol + 2] = h23;
            *(__half2*)&WsL[row * LDH + lcol]     = l01;
            *(__half2*)&WsL[row * LDH + lcol + 2] = l23;
        }
        __syncthreads();

        if (s + 1 < GK / 32) {
            const size_t ko = (size_t)(s + 1) * 32;
#pragma unroll
            for (int ir = 0; ir < 4; ++ir) {
                xr[ir] = *(const float4*)(Xg + (size_t)(32 * ir) * GK + ko);
                wr[ir] = *(const float4*)(Wg + (size_t)(32 * ir) * GK + ko);
            }
        }

#pragma unroll
        for (int k16 = 0; k16 < 2; ++k16) {
            const int k0 = k16 * 16;
            uint32_t bh[4][2], bl[4][2];
#pragma unroll
            for (int ni = 0; ni < 4; ++ni) {
                const int r = warp_n + ni * 8 + g;
                bh[ni][0] = U32AT(&WsH[r * LDH + k0 + 2 * tig]);
                bh[ni][1] = U32AT(&WsH[r * LDH + k0 + 8 + 2 * tig]);
                bl[ni][0] = U32AT(&WsL[r * LDH + k0 + 2 * tig]);
                bl[ni][1] = U32AT(&WsL[r * LDH + k0 + 8 + 2 * tig]);
            }
#pragma unroll
            for (int mi = 0; mi < 4; ++mi) {
                const int r0 = warp_m + mi * 16;
                uint32_t ah[4], al[4];
                ah[0] = U32AT(&XsH[(r0 + g)     * LDH + k0 + 2 * tig]);
                ah[1] = U32AT(&XsH[(r0 + g + 8) * LDH + k0 + 2 * tig]);
                ah[2] = U32AT(&XsH[(r0 + g)     * LDH + k0 + 8 + 2 * tig]);
                ah[3] = U32AT(&XsH[(r0 + g + 8) * LDH + k0 + 8 + 2 * tig]);
                al[0] = U32AT(&XsL[(r0 + g)     * LDH + k0 + 2 * tig]);
                al[1] = U32AT(&XsL[(r0 + g + 8) * LDH + k0 + 2 * tig]);
                al[2] = U32AT(&XsL[(r0 + g)     * LDH + k0 + 8 + 2 * tig]);
                al[3] = U32AT(&XsL[(r0 + g + 8) * LDH + k0 + 8 + 2 * tig]);
#pragma unroll
                for (int ni = 0; ni < 4; ++ni) {
                    mma_f16(acc[mi][ni], ah[0], ah[1], ah[2], ah[3], bh[ni][0], bh[ni][1]);
                    mma_f16(acc[mi][ni], ah[0], ah[1], ah[2], ah[3], bl[ni][0], bl[ni][1]);
                    mma_f16(acc[mi][ni], al[0], al[1], al[2], al[3], bh[ni][0], bh[ni][1]);
                }
            }
        }
    }

    // epilogue: write with bias
#pragma unroll
    for (int ni = 0; ni < 4; ++ni) {
        const int n = bn + warp_n + ni * 8 + 2 * tig;
        const float2 b2 = *(const float2*)(bias + n);
#pragma unroll
        for (int mi = 0; mi < 4; ++mi) {
            const int r0 = bm + warp_m + mi * 16;
            float2 o0, o1;
            o0.x = acc[mi][ni][0] + b2.x; o0.y = acc[mi][ni][1] + b2.y;
            o1.x = acc[mi][ni][2] + b2.x; o1.y = acc[mi][ni][3] + b2.y;
            *(float2*)(Y + (size_t)(r0 + g) * GN + n)     = o0;
            *(float2*)(Y + (size_t)(r0 + g + 8) * GN + n) = o1;
        }
    }
}

// ---------------- 3xFP16 tensor-core attention --------------------------------
// BQ=128 per block, BKT=64 per tile, 32 tiles, 8 warps (2m x 4n), m16n8k16.
// Register-prefetch of K (pass1) and S (pass2); V LDG issued early in tile.
#define AT_SMEM 56320
#define ALD 72

__global__ __launch_bounds__(256, 2) void attn_mma(float* __restrict__ atp) {
    extern __shared__ char sm[];
    __half* QH = (__half*)sm;
    __half* QL = (__half*)(sm + 18432);
    __half* KH = (__half*)(sm + 36864);
    __half* KL = (__half*)(sm + 46080);
    __half* PH = QH;
    __half* PL = QL;
    __half* VH = KH;
    __half* VL = KL;
    float* rowm  = (float*)(sm + 55296);
    float* rowil = (float*)(sm + 55808);
    float* mpart = (float*)sm;             // merge overlay (512 f)
    float* lpart = (float*)(sm + 2048);    // (512 f)

    const int t = threadIdx.x;
    const int w = t >> 5;
    const int lane = t & 31;
    const int g = lane >> 2;
    const int tig = lane & 3;
    const int wm = (w >> 2) * 64;
    const int wn = (w & 3) * 16;
    const int bh = blockIdx.y;
    const int b = bh >> 4, h = bh & 15;
    const int qt = blockIdx.x;
    const int q0 = qt * 128;

    const float* Qg = g_Q + ((size_t)(b * SS + q0)) * DD + h * DK;
    const float* Kg = g_K + ((size_t)(b * SS)) * DD + h * DK;
    const float* Vg = g_V + ((size_t)(b * SS)) * DD + h * DK;
    float* Sg = g_S + (((size_t)(bh * 16 + qt) * 32) * 256 + t) * 32;

    const int ldrow = t >> 4;       // 0..15 (row base for tile loads)
    const int ldc4  = t & 15;       // float4 column

    // ---- load Q 128x64 -> QH/QL ----
#pragma unroll
    for (int it = 0; it < 8; ++it) {
        int row = ldrow + 16 * it;
        float4 v = *(const float4*)(Qg + (size_t)row * DD + ldc4 * 4);
        __half2 h01, l01, h23, l23;
        split_h2(v.x, v.y, h01, l01);
        split_h2(v.z, v.w, h23, l23);
        int base = row * ALD + ldc4 * 4;
        *(__half2*)&QH[base]     = h01;
        *(__half2*)&QH[base + 2] = h23;
        *(__half2*)&QL[base]     = l01;
        *(__half2*)&QL[base + 2] = l23;
    }

    // ---- pass 1: scores + online (m,l) ----
    float m8[4][2], l8[4][2];
#pragma unroll
    for (int mi = 0; mi < 4; ++mi) {
        m8[mi][0] = -INFINITY; m8[mi][1] = -INFINITY;
        l8[mi][0] = 0.0f;      l8[mi][1] = 0.0f;
    }

    float4 kr[4];
#pragma unroll
    for (int it = 0; it < 4; ++it)
        kr[it] = *(const float4*)(Kg + (size_t)(ldrow + 16 * it) * DD + ldc4 * 4);

    for (int tile = 0; tile < 32; ++tile) {
        __syncthreads();
#pragma unroll
        for (int it = 0; it < 4; ++it) {
            int row = ldrow + 16 * it;
            __half2 h01, l01, h23, l23;
            split_h2(kr[it].x, kr[it].y, h01, l01);
            split_h2(kr[it].z, kr[it].w, h23, l23);
            int base = row * ALD + ldc4 * 4;
            *(__half2*)&KH[base]     = h01;
            *(__half2*)&KH[base + 2] = h23;
            *(__half2*)&KL[base]     = l01;
            *(__half2*)&KL[base + 2] = l23;
        }
        __syncthreads();

        if (tile + 1 < 32) {
#pragma unroll
            for (int it = 0; it < 4; ++it)
                kr[it] = *(const float4*)(Kg +
                    (size_t)((tile + 1) * 64 + ldrow + 16 * it) * DD + ldc4 * 4);
        }

        float sacc[4][2][4];
#pragma unroll
        for (int mi = 0; mi < 4; ++mi)
#pragma unroll
            for (int ni = 0; ni < 2; ++ni)
#pragma unroll
                for (int j = 0; j < 4; ++j) sacc[mi][ni][j] = 0.0f;

#pragma unroll
        for (int k16 = 0; k16 < 4; ++k16) {
            const int k0 = k16 * 16;
            uint32_t bhv[2][2], blv[2][2];
#pragma unroll
            for (int ni = 0; ni < 2; ++ni) {
                const int key = wn + ni * 8 + g;
                bhv[ni][0] = U32AT(&KH[key * ALD + k0 + 2 * tig]);
                bhv[ni][1] = U32AT(&KH[key * ALD + k0 + 8 + 2 * tig]);
                blv[ni][0] = U32AT(&KL[key * ALD + k0 + 2 * tig]);
                blv[ni][1] = U32AT(&KL[key * ALD + k0 + 8 + 2 * tig]);
            }
#pragma unroll
            for (int mi = 0; mi < 4; ++mi) {
                const int r0 = wm + mi * 16;
                uint32_t ah[4], al[4];
                ah[0] = U32AT(&QH[(r0 + g)     * ALD + k0 + 2 * tig]);
                ah[1] = U32AT(&QH[(r0 + g + 8) * ALD + k0 + 2 * tig]);
                ah[2] = U32AT(&QH[(r0 + g)     * ALD + k0 + 8 + 2 * tig]);
                ah[3] = U32AT(&QH[(r0 + g + 8) * ALD + k0 + 8 + 2 * tig]);
                al[0] = U32AT(&QL[(r0 + g)     * ALD + k0 + 2 * tig]);
                al[1] = U32AT(&QL[(r0 + g + 8) * ALD + k0 + 2 * tig]);
                al[2] = U32AT(&QL[(r0 + g)     * ALD + k0 + 8 + 2 * tig]);
                al[3] = U32AT(&QL[(r0 + g + 8) * ALD + k0 + 8 + 2 * tig]);
#pragma unroll
                for (int ni = 0; ni < 2; ++ni) {
                    mma_f16(sacc[mi][ni], ah[0], ah[1], ah[2], ah[3], bhv[ni][0], bhv[ni][1]);
                    mma_f16(sacc[mi][ni], ah[0], ah[1], ah[2], ah[3], blv[ni][0], blv[ni][1]);
                    mma_f16(sacc[mi][ni], al[0], al[1], al[2], al[3], bhv[ni][0], bhv[ni][1]);
                }
            }
        }

        // scale, store to scratch, online update
        float* Sp = Sg + (size_t)tile * 8192;
#pragma unroll
        for (int mi = 0; mi < 4; ++mi) {
#pragma unroll
            for (int ni = 0; ni < 2; ++ni) {
#pragma unroll
                for (int j = 0; j < 4; ++j) sacc[mi][ni][j] *= SCALE;
                *(float4*)(Sp + (mi * 2 + ni) * 4) =
                    make_float4(sacc[mi][ni][0], sacc[mi][ni][1],
                                sacc[mi][ni][2], sacc[mi][ni][3]);
            }
#pragma unroll
            for (int r = 0; r < 2; ++r) {
                float v0 = sacc[mi][0][r*2], v1 = sacc[mi][0][r*2+1];
                float v2 = sacc[mi][1][r*2], v3 = sacc[mi][1][r*2+1];
                float mx = fmaxf(fmaxf(v0, v1), fmaxf(v2, v3));
                float mo = m8[mi][r];
                float mn = fmaxf(mo, mx);
                l8[mi][r] = l8[mi][r] * __expf(mo - mn)
                          + __expf(v0 - mn) + __expf(v1 - mn)
                          + __expf(v2 - mn) + __expf(v3 - mn);
                m8[mi][r] = mn;
            }
        }
    }

    // ---- merge (m,l) ----
    __syncthreads();
#pragma unroll
    for (int mi = 0; mi < 4; ++mi)
#pragma unroll
        for (int r = 0; r < 2; ++r) {
            float m = m8[mi][r], l = l8[mi][r];
#pragma unroll
            for (int off = 1; off <= 2; off <<= 1) {
                float mo = __shfl_xor_sync(0xffffffffu, m, off);
                float lo = __shfl_xor_sync(0xffffffffu, l, off);
                float mn = fmaxf(m, mo);
                l = l * __expf(m - mn) + lo * __expf(mo - mn);
                m = mn;
            }
            if (tig == 0) {
                int row = wm + mi * 16 + g + r * 8;
                mpart[(w & 3) * 128 + row] = m;
                lpart[(w & 3) * 128 + row] = l;
            }
        }
    __syncthreads();
    if (t < 128) {
        float m = mpart[t], l = lpart[t];
#pragma unroll
        for (int p = 1; p < 4; ++p) {
            float mo = mpart[p * 128 + t], lo = lpart[p * 128 + t];
            float mn = fmaxf(m, mo);
            l = l * __expf(m - mn) + lo * __expf(mo - mn);
            m = mn;
        }
        rowm[t] = m;
        rowil[t] = 1.0f / l;
    }
    __syncthreads();

    // ---- pass 2 ----
    float my_m[4][2], my_il[4][2];
#pragma unroll
    for (int mi = 0; mi < 4; ++mi)
#pragma unroll
        for (int r = 0; r < 2; ++r) {
            int row = wm + mi * 16 + g + r * 8;
            my_m[mi][r] = rowm[row];
            my_il[mi][r] = rowil[row];
        }

    float oacc[4][2][4];
#pragma unroll
    for (int mi = 0; mi < 4; ++mi)
#pragma unroll
        for (int ni = 0; ni < 2; ++ni)
#pragma unroll
            for (int j = 0; j < 4; ++j) oacc[mi][ni][j] = 0.0f;

    float4 sreg[8];
#pragma unroll
    for (int i = 0; i < 8; ++i)
        sreg[i] = *(const float4*)(Sg + i * 4);

    for (int tile = 0; tile < 32; ++tile) {
        __syncthreads();

        // issue V LDGs early; latency hidden behind exp/split below
        float4 vr[4];
#pragma unroll
        for (int it = 0; it < 4; ++it)
            vr[it] = *(const float4*)(Vg +
                (size_t)(tile * 64 + ldrow + 16 * it) * DD + ldc4 * 4);

        // S regs -> P (exact fp32) -> colsum + split to PH/PL
        float csum[2][2] = {{0.f, 0.f}, {0.f, 0.f}};
#pragma unroll
        for (int mi = 0; mi < 4; ++mi)
#pragma unroll
            for (int ni = 0; ni < 2; ++ni) {
                float4 s4 = sreg[mi * 2 + ni];
                float p0 = __expf(s4.x - my_m[mi][0]) * my_il[mi][0];
                float p1 = __expf(s4.y - my_m[mi][0]) * my_il[mi][0];
                float p2 = __expf(s4.z - my_m[mi][1]) * my_il[mi][1];
                float p3 = __expf(s4.w - my_m[mi][1]) * my_il[mi][1];
                csum[ni][0] += p0 + p2;
                csum[ni][1] += p1 + p3;
                __half2 hA, lA, hB, lB;
                split_h2(p0, p1, hA, lA);
                split_h2(p2, p3, hB, lB);
                int col = wn + ni * 8 + 2 * tig;
                int r0 = wm + mi * 16 + g;
                *(__half2*)&PH[r0 * ALD + col]       = hA;
                *(__half2*)&PL[r0 * ALD + col]       = lA;
                *(__half2*)&PH[(r0 + 8) * ALD + col] = hB;
                *(__half2*)&PL[(r0 + 8) * ALD + col] = lB;
            }

        // colsum reduce over g lanes, atomicAdd
#pragma unroll
        for (int ni = 0; ni < 2; ++ni)
#pragma unroll
            for (int c = 0; c < 2; ++c) {
                float v = csum[ni][c];
                v += __shfl_xor_sync(0xffffffffu, v, 4);
                v += __shfl_xor_sync(0xffffffffu, v, 8);
                v += __shfl_xor_sync(0xffffffffu, v, 16);
                if (lane < 4)
                    atomicAdd(&atp[b * SS + tile * 64 + wn + ni * 8 + 2 * tig + c],
                              v * INV_HS);
            }

        // V split-store (transposed): VH/VL [dk][key]
#pragma unroll
        for (int it = 0; it < 4; ++it) {
            int row = ldrow + 16 * it;
            float vv[4] = {vr[it].x, vr[it].y, vr[it].z, vr[it].w};
#pragma unroll
            for (int j = 0; j < 4; ++j) {
                __half hh = __float2half_rn(vv[j]);
                __half ll = __float2half_rn(vv[j] - __half2float(hh));
                VH[(ldc4 * 4 + j) * ALD + row] = hh;
                VL[(ldc4 * 4 + j) * ALD + row] = ll;
            }
        }
        __syncthreads();

        // prefetch next S block while PV MMA runs
        if (tile + 1 < 32) {
            const float* Sn = Sg + (size_t)(tile + 1) * 8192;
#pragma unroll
            for (int i = 0; i < 8; ++i)
                sreg[i] = *(const float4*)(Sn + i * 4);
        }

        // PV mma: A = P, B = V^T
#pragma unroll
        for (int k16 = 0; k16 < 4; ++k16) {
            const int k0 = k16 * 16;
            uint32_t bhv[2][2], blv[2][2];
#pragma unroll
            for (int ni = 0; ni < 2; ++ni) {
                const int dk = wn + ni * 8 + g;
                bhv[ni][0] = U32AT(&VH[dk * ALD + k0 + 2 * tig]);
                bhv[ni][1] = U32AT(&VH[dk * ALD + k0 + 8 + 2 * tig]);
                blv[ni][0] = U32AT(&VL[dk * ALD + k0 + 2 * tig]);
                blv[ni][1] = U32AT(&VL[dk * ALD + k0 + 8 + 2 * tig]);
            }
#pragma unroll
            for (int mi = 0; mi < 4; ++mi) {
                const int r0 = wm + mi * 16;
                uint32_t ah[4], al[4];
                ah[0] = U32AT(&PH[(r0 + g)     * ALD + k0 + 2 * tig]);
                ah[1] = U32AT(&PH[(r0 + g + 8) * ALD + k0 + 2 * tig]);
                ah[2] = U32AT(&PH[(r0 + g)     * ALD + k0 + 8 + 2 * tig]);
                ah[3] = U32AT(&PH[(r0 + g + 8) * ALD + k0 + 8 + 2 * tig]);
                al[0] = U32AT(&PL[(r0 + g)     * ALD + k0 + 2 * tig]);
                al[1] = U32AT(&PL[(r0 + g + 8) * ALD + k0 + 2 * tig]);
                al[2] = U32AT(&PL[(r0 + g)     * ALD + k0 + 8 + 2 * tig]);
                al[3] = U32AT(&PL[(r0 + g + 8) * ALD + k0 + 8 + 2 * tig]);
#pragma unroll
                for (int ni = 0; ni < 2; ++ni) {
                    mma_f16(oacc[mi][ni], ah[0], ah[1], ah[2], ah[3], bhv[ni][0], bhv[ni][1]);
                    mma_f16(oacc[mi][ni], ah[0], ah[1], ah[2], ah[3], blv[ni][0], blv[ni][1]);
                    mma_f16(oacc[mi][ni], al[0], al[1], al[2], al[3], bhv[ni][0], bhv[ni][1]);
                }
            }
        }
    }

    // ---- epilogue: write context ----
    float* Cg = g_C + ((size_t)(b * SS + q0)) * DD + h * DK;
#pragma unroll
    for (int mi = 0; mi < 4; ++mi)
#pragma unroll
        for (int ni = 0; ni < 2; ++ni) {
            const int col = wn + ni * 8 + 2 * tig;
            const int r0 = wm + mi * 16 + g;
            *(float2*)(Cg + (size_t)r0 * DD + col) =
                make_float2(oacc[mi][ni][0], oacc[mi][ni][1]);
            *(float2*)(Cg + (size_t)(r0 + 8) * DD + col) =
                make_float2(oacc[mi][ni][2], oacc[mi][ni][3]);
        }
}

// ---------------- launch ------------------------------------------------------
extern "C" void kernel_launch(void* const* d_in, const int* in_sizes, int n_in,
                              void* d_out, int out_size) {
    (void)in_sizes; (void)n_in; (void)out_size;
    const float* query = (const float*)d_in[0];
    const float* key   = (const float*)d_in[1];
    const float* value = (const float*)d_in[2];
    const float* Wq = (const float*)d_in[3];
    const float* bq = (const float*)d_in[4];
    const float* Wk = (const float*)d_in[5];
    const float* bk = (const float*)d_in[6];
    const float* Wv = (const float*)d_in[7];
    const float* bv = (const float*)d_in[8];
    const float* Wo = (const float*)d_in[9];
    const float* bo = (const float*)d_in[10];

    float* out = (float*)d_out;
    float* atp = out + (size_t)BB * SS * DD;

    float *Qp, *Kp, *Vp, *Cp;
    cudaGetSymbolAddress((void**)&Qp, g_Q);
    cudaGetSymbolAddress((void**)&Kp, g_K);
    cudaGetSymbolAddress((void**)&Vp, g_V);
    cudaGetSymbolAddress((void**)&Cp, g_C);

    zero_atp_kernel<<<(BB*SS + 255) / 256, 256>>>(atp);

    cudaFuncSetAttribute(gemm_h, cudaFuncAttributeMaxDynamicSharedMemorySize,
                         GEMM_SMEM);
    cudaFuncSetAttribute(attn_mma, cudaFuncAttributeMaxDynamicSharedMemorySize,
                         AT_SMEM);

    dim3 gg(GN / 128, MTOT / 128);
    gemm_h<<<gg, 256, GEMM_SMEM>>>(query, Wq, bq, Qp);
    gemm_h<<<gg, 256, GEMM_SMEM>>>(key,   Wk, bk, Kp);
    gemm_h<<<gg, 256, GEMM_SMEM>>>(value, Wv, bv, Vp);

    attn_mma<<<dim3(16, 32), 256, AT_SMEM>>>(atp);

    gemm_h<<<gg, 256, GEMM_SMEM>>>(Cp, Wo, bo, out);
}

// round 8
// speedup vs baseline: 1.3359x; 1.3359x over previous
#include <cuda_runtime.h>
#include <cuda_fp16.h>
#include <math.h>
#include <stdint.h>

#define BB 2
#define SS 2048
#define DD 1024
#define HH 16
#define DK 64
#define MTOT (BB*SS)

#define SCALE 12.5f                  // 100/sqrt(64)
#define INV_HS (1.0f/32768.0f)       // 1/(H*S)

// ---------------- scratch (static device globals; no allocation) -------------
__device__ float g_Q[MTOT*DD];
__device__ float g_K[MTOT*DD];
__device__ float g_V[MTOT*DD];
__device__ float g_C[MTOT*DD];
// u = exp(s - m_tile) stored as packed fp16 pairs:
// layout ((blk*32 + tile)*16 + i)*256 + t   -> 512*32*16*256 u32 = 256MB
__device__ uint32_t g_U[512ull * 32 * 16 * 256];

// ---------------- helpers -----------------------------------------------------
__device__ __forceinline__ void split_h2(float a, float b, __half2& h, __half2& l) {
    h = __floats2half2_rn(a, b);
    float2 f = __half22float2(h);
    l = __floats2half2_rn(a - f.x, b - f.y);
}

__device__ __forceinline__ void split_pack(float a, float b, uint32_t& h, uint32_t& l) {
    __half2 hh, ll;
    split_h2(a, b, hh, ll);
    h = *(uint32_t*)&hh;
    l = *(uint32_t*)&ll;
}

__device__ __forceinline__ void mma_f16(float c[4],
                                        uint32_t a0, uint32_t a1, uint32_t a2, uint32_t a3,
                                        uint32_t b0, uint32_t b1) {
    asm volatile(
        "mma.sync.aligned.m16n8k16.row.col.f32.f16.f16.f32 "
        "{%0,%1,%2,%3}, {%4,%5,%6,%7}, {%8,%9}, {%0,%1,%2,%3};"
        : "+f"(c[0]), "+f"(c[1]), "+f"(c[2]), "+f"(c[3])
        : "r"(a0), "r"(a1), "r"(a2), "r"(a3), "r"(b0), "r"(b1));
}

#define U32AT(p) (*(const uint32_t*)(p))

// ---------------- zero mean_atp region ---------------------------------------
__global__ void zero_atp_kernel(float* __restrict__ atp) {
    int i = blockIdx.x * blockDim.x + threadIdx.x;
    if (i < BB*SS) atp[i] = 0.0f;
}

// ---------------- 3xFP16 mma.sync GEMM (R6 version, no prefetch) --------------
#define GK 1024
#define GN 1024
#define LDH 40                         // halfs per smem row (32 + 8 pad)
#define GEMM_SMEM 40960                // XsH,XsL,WsH,WsL: 4 * 128*40*2 bytes

__global__ __launch_bounds__(256, 2) void gemm_h(
    const float* __restrict__ X, const float* __restrict__ W,
    const float* __restrict__ bias, float* __restrict__ Y)
{
    extern __shared__ char sm[];
    __half* XsH = (__half*)sm;                     // [128][40]
    __half* XsL = (__half*)(sm + 10240);
    __half* WsH = (__half*)(sm + 20480);
    __half* WsL = (__half*)(sm + 30720);

    const int t = threadIdx.x;
    const int w = t >> 5;
    const int lane = t & 31;
    const int g = lane >> 2;
    const int tig = lane & 3;
    const int warp_m = (w >> 2) * 64;
    const int warp_n = (w & 3) * 32;
    const int bm = blockIdx.y * 128;
    const int bn = blockIdx.x * 128;

    const int lrow = t >> 3;              // 0..31
    const int lcol = (t & 7) * 4;         // 0..28

    float acc[4][4][4];
#pragma unroll
    for (int mi = 0; mi < 4; ++mi)
#pragma unroll
        for (int ni = 0; ni < 4; ++ni)
#pragma unroll
            for (int j = 0; j < 4; ++j) acc[mi][ni][j] = 0.0f;

    const float* Xg = X + (size_t)(bm + lrow) * GK + lcol;
    const float* Wg = W + (size_t)(bn + lrow) * GK + lcol;

    for (int s = 0; s < GK / 32; ++s) {
        __syncthreads();
#pragma unroll
        for (int ir = 0; ir < 4; ++ir) {
            const int row = lrow + 32 * ir;
            float4 xv = *(const float4*)(Xg + (size_t)(32 * ir) * GK + s * 32);
            float4 wv = *(const float4*)(Wg + (size_t)(32 * ir) * GK + s * 32);
            __half2 h01, l01, h23, l23;
            split_h2(xv.x, xv.y, h01, l01);
            split_h2(xv.z, xv.w, h23, l23);
            *(__half2*)&XsH[row * LDH + lcol]     = h01;
            *(__half2*)&XsH[row * LDH + lcol + 2] = h23;
            *(__half2*)&XsL[row * LDH + lcol]     = l01;
            *(__half2*)&XsL[row * LDH + lcol + 2] = l23;
            split_h2(wv.x, wv.y, h01, l01);
            split_h2(wv.z, wv.w, h23, l23);
            *(__half2*)&WsH[row * LDH + lcol]     = h01;
            *(__half2*)&WsH[row * LDH + lcol + 2] = h23;
            *(__half2*)&WsL[row * LDH + lcol]     = l01;
            *(__half2*)&WsL[row * LDH + lcol + 2] = l23;
        }
        __syncthreads();

#pragma unroll
        for (int k16 = 0; k16 < 2; ++k16) {
            const int k0 = k16 * 16;
            uint32_t bh[4][2], bl[4][2];
#pragma unroll
            for (int ni = 0; ni < 4; ++ni) {
                const int r = warp_n + ni * 8 + g;
                bh[ni][0] = U32AT(&WsH[r * LDH + k0 + 2 * tig]);
                bh[ni][1] = U32AT(&WsH[r * LDH + k0 + 8 + 2 * tig]);
                bl[ni][0] = U32AT(&WsL[r * LDH + k0 + 2 * tig]);
                bl[ni][1] = U32AT(&WsL[r * LDH + k0 + 8 + 2 * tig]);
            }
#pragma unroll
            for (int mi = 0; mi < 4; ++mi) {
                const int r0 = warp_m + mi * 16;
                uint32_t ah[4], al[4];
                ah[0] = U32AT(&XsH[(r0 + g)     * LDH + k0 + 2 * tig]);
                ah[1] = U32AT(&XsH[(r0 + g + 8) * LDH + k0 + 2 * tig]);
                ah[2] = U32AT(&XsH[(r0 + g)     * LDH + k0 + 8 + 2 * tig]);
                ah[3] = U32AT(&XsH[(r0 + g + 8) * LDH + k0 + 8 + 2 * tig]);
                al[0] = U32AT(&XsL[(r0 + g)     * LDH + k0 + 2 * tig]);
                al[1] = U32AT(&XsL[(r0 + g + 8) * LDH + k0 + 2 * tig]);
                al[2] = U32AT(&XsL[(r0 + g)     * LDH + k0 + 8 + 2 * tig]);
                al[3] = U32AT(&XsL[(r0 + g + 8) * LDH + k0 + 8 + 2 * tig]);
#pragma unroll
                for (int ni = 0; ni < 4; ++ni) {
                    mma_f16(acc[mi][ni], ah[0], ah[1], ah[2], ah[3], bh[ni][0], bh[ni][1]);
                    mma_f16(acc[mi][ni], ah[0], ah[1], ah[2], ah[3], bl[ni][0], bl[ni][1]);
                    mma_f16(acc[mi][ni], al[0], al[1], al[2], al[3], bh[ni][0], bh[ni][1]);
                }
            }
        }
    }

#pragma unroll
    for (int ni = 0; ni < 4; ++ni) {
        const int n = bn + warp_n + ni * 8 + 2 * tig;
        const float2 b2 = *(const float2*)(bias + n);
#pragma unroll
        for (int mi = 0; mi < 4; ++mi) {
            const int r0 = bm + warp_m + mi * 16;
            float2 o0, o1;
            o0.x = acc[mi][ni][0] + b2.x; o0.y = acc[mi][ni][1] + b2.y;
            o1.x = acc[mi][ni][2] + b2.x; o1.y = acc[mi][ni][3] + b2.y;
            *(float2*)(Y + (size_t)(r0 + g) * GN + n)     = o0;
            *(float2*)(Y + (size_t)(r0 + g + 8) * GN + n) = o1;
        }
    }
}

// ---------------- single-pass fused flash attention ---------------------------
// 8 warps x 16 q-rows = 128 q per block; 32 key tiles of 64.
// Q frags register-resident; P never touches smem (C-frag -> A-frag reuse).
// u=exp(s-m) stored fp16 to g_U; colsum readback phase after mainloop.
// smem: KH@0 KL@9216 VH@18432 VL@27648 (each 64x72 halfs = 9216B)
//       mhist@36864 [32][128] f32 (16384B)   red@53248 [8][64] f32 (2048B)
#define ALD 72
#define AT_SMEM 55296

__global__ __launch_bounds__(256, 2) void attn_fused(float* __restrict__ atp) {
    extern __shared__ char sm[];
    __half* KH = (__half*)sm;
    __half* KL = (__half*)(sm + 9216);
    __half* VH = (__half*)(sm + 18432);   // transposed: [dk][key]
    __half* VL = (__half*)(sm + 27648);
    float* mhist = (float*)(sm + 36864);  // [tile][128]
    float* red   = (float*)(sm + 53248);  // [warp][64]

    const int t = threadIdx.x;
    const int w = t >> 5;
    const int lane = t & 31;
    const int g = lane >> 2;
    const int tig = lane & 3;
    const int bh = blockIdx.y;
    const int b = bh >> 4, h = bh & 15;
    const int qt = blockIdx.x;
    const int q0 = qt * 128;
    const int blk = bh * 16 + qt;

    const float* Qg = g_Q + ((size_t)(b * SS + q0 + 16 * w)) * DD + h * DK;
    const float* Kg = g_K + ((size_t)(b * SS)) * DD + h * DK;
    const float* Vg = g_V + ((size_t)(b * SS)) * DD + h * DK;

    const int ldrow = t >> 4;       // 0..15
    const int ldc4  = t & 15;       // 0..15

    // ---- Q fragments: register-resident for the whole kernel ----
    uint32_t qh[4][4], ql[4][4];
#pragma unroll
    for (int j = 0; j < 4; ++j) {
        float2 x0 = *(const float2*)(Qg + (size_t)g * DD + 16 * j + 2 * tig);
        float2 x1 = *(const float2*)(Qg + (size_t)(g + 8) * DD + 16 * j + 2 * tig);
        float2 x2 = *(const float2*)(Qg + (size_t)g * DD + 16 * j + 8 + 2 * tig);
        float2 x3 = *(const float2*)(Qg + (size_t)(g + 8) * DD + 16 * j + 8 + 2 * tig);
        split_pack(x0.x, x0.y, qh[j][0], ql[j][0]);
        split_pack(x1.x, x1.y, qh[j][1], ql[j][1]);
        split_pack(x2.x, x2.y, qh[j][2], ql[j][2]);
        split_pack(x3.x, x3.y, qh[j][3], ql[j][3]);
    }

    float oacc[8][4];
#pragma unroll
    for (int ni = 0; ni < 8; ++ni)
#pragma unroll
        for (int j = 0; j < 4; ++j) oacc[ni][j] = 0.0f;

    float m0 = -INFINITY, m1 = -INFINITY, l0 = 0.0f, l1 = 0.0f;

    for (int tile = 0; tile < 32; ++tile) {
        __syncthreads();
        // ---- load K tile [key][dk] + V tile transposed [dk][key], split hi/lo
#pragma unroll
        for (int it = 0; it < 4; ++it) {
            const int row = ldrow + 16 * it;
            float4 kv = *(const float4*)(Kg + (size_t)(tile * 64 + row) * DD + ldc4 * 4);
            __half2 h01, l01, h23, l23;
            split_h2(kv.x, kv.y, h01, l01);
            split_h2(kv.z, kv.w, h23, l23);
            const int base = row * ALD + ldc4 * 4;
            *(__half2*)&KH[base]     = h01;
            *(__half2*)&KH[base + 2] = h23;
            *(__half2*)&KL[base]     = l01;
            *(__half2*)&KL[base + 2] = l23;

            float4 vv = *(const float4*)(Vg + (size_t)(tile * 64 + row) * DD + ldc4 * 4);
            float vvv[4] = {vv.x, vv.y, vv.z, vv.w};
#pragma unroll
            for (int jj = 0; jj < 4; ++jj) {
                __half hh = __float2half_rn(vvv[jj]);
                __half ll = __float2half_rn(vvv[jj] - __half2float(hh));
                VH[(ldc4 * 4 + jj) * ALD + row] = hh;
                VL[(ldc4 * 4 + jj) * ALD + row] = ll;
            }
        }
        __syncthreads();

        // ---- QK^T: s[16q x 64k] per warp ----
        float sacc[8][4];
#pragma unroll
        for (int ni = 0; ni < 8; ++ni)
#pragma unroll
            for (int j = 0; j < 4; ++j) sacc[ni][j] = 0.0f;

#pragma unroll
        for (int j = 0; j < 4; ++j) {
#pragma unroll
            for (int ni = 0; ni < 8; ++ni) {
                const int key = ni * 8 + g;
                uint32_t bh0 = U32AT(&KH[key * ALD + 16 * j + 2 * tig]);
                uint32_t bh1 = U32AT(&KH[key * ALD + 16 * j + 8 + 2 * tig]);
                uint32_t bl0 = U32AT(&KL[key * ALD + 16 * j + 2 * tig]);
                uint32_t bl1 = U32AT(&KL[key * ALD + 16 * j + 8 + 2 * tig]);
                mma_f16(sacc[ni], qh[j][0], qh[j][1], qh[j][2], qh[j][3], bh0, bh1);
                mma_f16(sacc[ni], qh[j][0], qh[j][1], qh[j][2], qh[j][3], bl0, bl1);
                mma_f16(sacc[ni], ql[j][0], ql[j][1], ql[j][2], ql[j][3], bh0, bh1);
            }
        }

        // ---- scale + row max (row g -> c0,c1 ; row g+8 -> c2,c3) ----
        float mx0 = -INFINITY, mx1 = -INFINITY;
#pragma unroll
        for (int ni = 0; ni < 8; ++ni) {
            sacc[ni][0] *= SCALE; sacc[ni][1] *= SCALE;
            sacc[ni][2] *= SCALE; sacc[ni][3] *= SCALE;
            mx0 = fmaxf(mx0, fmaxf(sacc[ni][0], sacc[ni][1]));
            mx1 = fmaxf(mx1, fmaxf(sacc[ni][2], sacc[ni][3]));
        }
        mx0 = fmaxf(mx0, __shfl_xor_sync(0xffffffffu, mx0, 1));
        mx0 = fmaxf(mx0, __shfl_xor_sync(0xffffffffu, mx0, 2));
        mx1 = fmaxf(mx1, __shfl_xor_sync(0xffffffffu, mx1, 1));
        mx1 = fmaxf(mx1, __shfl_xor_sync(0xffffffffu, mx1, 2));

        const float mn0 = fmaxf(m0, mx0);
        const float mn1 = fmaxf(m1, mx1);
        const float al0 = __expf(m0 - mn0);
        const float al1 = __expf(m1 - mn1);
        m0 = mn0; m1 = mn1;

        // ---- u = exp(s-m); store fp16 to scratch; keep fp32 in sacc for PV ----
        const size_t ubase = ((size_t)(blk * 32 + tile) * 16) * 256 + t;
        float ls0 = 0.0f, ls1 = 0.0f;
#pragma unroll
        for (int ni = 0; ni < 8; ++ni) {
            float u0 = __expf(sacc[ni][0] - m0);
            float u1 = __expf(sacc[ni][1] - m0);
            float u2 = __expf(sacc[ni][2] - m1);
            float u3 = __expf(sacc[ni][3] - m1);
            ls0 += u0 + u1; ls1 += u2 + u3;
            __half2 p01 = __floats2half2_rn(u0, u1);
            __half2 p23 = __floats2half2_rn(u2, u3);
            g_U[ubase + (size_t)(2 * ni) * 256]     = *(uint32_t*)&p01;
            g_U[ubase + (size_t)(2 * ni + 1) * 256] = *(uint32_t*)&p23;
            sacc[ni][0] = u0; sacc[ni][1] = u1;
            sacc[ni][2] = u2; sacc[ni][3] = u3;
        }
        l0 = l0 * al0 + ls0;
        l1 = l1 * al1 + ls1;

        if (tig == 0) {
            mhist[tile * 128 + 16 * w + g]     = m0;
            mhist[tile * 128 + 16 * w + g + 8] = m1;
        }

        // ---- rescale O ----
#pragma unroll
        for (int ni = 0; ni < 8; ++ni) {
            oacc[ni][0] *= al0; oacc[ni][1] *= al0;
            oacc[ni][2] *= al1; oacc[ni][3] *= al1;
        }

        // ---- PV: A = u (C-frag -> A-frag register reuse), B = V^T ----
#pragma unroll
        for (int j = 0; j < 4; ++j) {
            uint32_t ah0, ah1, ah2, ah3, aL0, aL1, aL2, aL3;
            split_pack(sacc[2*j][0],   sacc[2*j][1],   ah0, aL0);
            split_pack(sacc[2*j][2],   sacc[2*j][3],   ah1, aL1);
            split_pack(sacc[2*j+1][0], sacc[2*j+1][1], ah2, aL2);
            split_pack(sacc[2*j+1][2], sacc[2*j+1][3], ah3, aL3);
#pragma unroll
            for (int ni = 0; ni < 8; ++ni) {
                const int dk = ni * 8 + g;
                uint32_t bh0 = U32AT(&VH[dk * ALD + 16 * j + 2 * tig]);
                uint32_t bh1 = U32AT(&VH[dk * ALD + 16 * j + 8 + 2 * tig]);
                uint32_t bl0 = U32AT(&VL[dk * ALD + 16 * j + 2 * tig]);
                uint32_t bl1 = U32AT(&VL[dk * ALD + 16 * j + 8 + 2 * tig]);
                mma_f16(oacc[ni], ah0, ah1, ah2, ah3, bh0, bh1);
                mma_f16(oacc[ni], ah0, ah1, ah2, ah3, bl0, bl1);
                mma_f16(oacc[ni], aL0, aL1, aL2, aL3, bh0, bh1);
            }
        }
    }

    // ---- merge l over tig lanes; write O ----
    l0 += __shfl_xor_sync(0xffffffffu, l0, 1);
    l0 += __shfl_xor_sync(0xffffffffu, l0, 2);
    l1 += __shfl_xor_sync(0xffffffffu, l1, 1);
    l1 += __shfl_xor_sync(0xffffffffu, l1, 2);
    const float il0 = 1.0f / l0;
    const float il1 = 1.0f / l1;

    float* Cg = g_C + ((size_t)(b * SS + q0 + 16 * w)) * DD + h * DK;
#pragma unroll
    for (int ni = 0; ni < 8; ++ni) {
        const int col = ni * 8 + 2 * tig;
        *(float2*)(Cg + (size_t)g * DD + col) =
            make_float2(oacc[ni][0] * il0, oacc[ni][1] * il0);
        *(float2*)(Cg + (size_t)(g + 8) * DD + col) =
            make_float2(oacc[ni][2] * il1, oacc[ni][3] * il1);
    }

    __syncthreads();   // mhist visible to all lanes; smem K/V no longer needed

    // ---- colsum readback: p = u * exp(m_t - m_f) * il ; reduce per key ----
    for (int tile = 0; tile < 32; ++tile) {
        const size_t ubase = ((size_t)(blk * 32 + tile) * 16) * 256 + t;
        uint32_t uu[16];
#pragma unroll
        for (int i = 0; i < 16; ++i)
            uu[i] = g_U[ubase + (size_t)i * 256];
        const float w0 = __expf(mhist[tile * 128 + 16 * w + g]     - m0) * il0;
        const float w1 = __expf(mhist[tile * 128 + 16 * w + g + 8] - m1) * il1;

#pragma unroll
        for (int ni = 0; ni < 8; ++ni) {
            float2 fa = __half22float2(*(__half2*)&uu[2 * ni]);
            float2 fb = __half22float2(*(__half2*)&uu[2 * ni + 1]);
            float cs0 = fa.x * w0 + fb.x * w1;    // key = 8ni + 2tig
            float cs1 = fa.y * w0 + fb.y * w1;    // key = 8ni + 2tig + 1
            cs0 += __shfl_xor_sync(0xffffffffu, cs0, 4);
            cs0 += __shfl_xor_sync(0xffffffffu, cs0, 8);
            cs0 += __shfl_xor_sync(0xffffffffu, cs0, 16);
            cs1 += __shfl_xor_sync(0xffffffffu, cs1, 4);
            cs1 += __shfl_xor_sync(0xffffffffu, cs1, 8);
            cs1 += __shfl_xor_sync(0xffffffffu, cs1, 16);
            if (lane < 4) {
                red[w * 64 + ni * 8 + 2 * tig]     = cs0;
                red[w * 64 + ni * 8 + 2 * tig + 1] = cs1;
            }
        }
        __syncthreads();
        if (t < 64) {
            float s = 0.0f;
#pragma unroll
            for (int wi = 0; wi < 8; ++wi) s += red[wi * 64 + t];
            atomicAdd(&atp[b * SS + tile * 64 + t], s * INV_HS);
        }
        __syncthreads();
    }
}

// ---------------- launch ------------------------------------------------------
extern "C" void kernel_launch(void* const* d_in, const int* in_sizes, int n_in,
                              void* d_out, int out_size) {
    (void)in_sizes; (void)n_in; (void)out_size;
    const float* query = (const float*)d_in[0];
    const float* key   = (const float*)d_in[1];
    const float* value = (const float*)d_in[2];
    const float* Wq = (const float*)d_in[3];
    const float* bq = (const float*)d_in[4];
    const float* Wk = (const float*)d_in[5];
    const float* bk = (const float*)d_in[6];
    const float* Wv = (const float*)d_in[7];
    const float* bv = (const float*)d_in[8];
    const float* Wo = (const float*)d_in[9];
    const float* bo = (const float*)d_in[10];

    float* out = (float*)d_out;
    float* atp = out + (size_t)BB * SS * DD;

    float *Qp, *Kp, *Vp, *Cp;
    cudaGetSymbolAddress((void**)&Qp, g_Q);
    cudaGetSymbolAddress((void**)&Kp, g_K);
    cudaGetSymbolAddress((void**)&Vp, g_V);
    cudaGetSymbolAddress((void**)&Cp, g_C);

    zero_atp_kernel<<<(BB*SS + 255) / 256, 256>>>(atp);

    cudaFuncSetAttribute(gemm_h, cudaFuncAttributeMaxDynamicSharedMemorySize,
                         GEMM_SMEM);
    cudaFuncSetAttribute(attn_fused, cudaFuncAttributeMaxDynamicSharedMemorySize,
                         AT_SMEM);

    dim3 gg(GN / 128, MTOT / 128);
    gemm_h<<<gg, 256, GEMM_SMEM>>>(query, Wq, bq, Qp);
    gemm_h<<<gg, 256, GEMM_SMEM>>>(key,   Wk, bk, Kp);
    gemm_h<<<gg, 256, GEMM_SMEM>>>(value, Wv, bv, Vp);

    attn_fused<<<dim3(16, 32), 256, AT_SMEM>>>(atp);

    gemm_h<<<gg, 256, GEMM_SMEM>>>(Cp, Wo, bo, out);
}

// round 9
// speedup vs baseline: 1.4393x; 1.0774x over previous
#include <cuda_runtime.h>
#include <cuda_fp16.h>
#include <math.h>
#include <stdint.h>

#define BB 2
#define SS 2048
#define DD 1024
#define HH 16
#define DK 64
#define MTOT (BB*SS)

#define SCALE 12.5f                  // 100/sqrt(64)
#define INV_HS (1.0f/32768.0f)       // 1/(H*S)

// ---------------- device scratch ----------------------------------------------
// split inputs: query@0, key@4M, value@8M, Wq@12M, Wk@13M, Wv@14M, Wo@15M (halfs)
__device__ __half g_inH[16777216];
__device__ __half g_inL[16777216];
__device__ __half g_QH[4194304], g_QL[4194304];
__device__ __half g_KH[4194304], g_KL[4194304];
__device__ __half g_VtH[4194304], g_VtL[4194304];   // [b*1024+n][2048] transposed
__device__ __half g_CH[4194304], g_CL[4194304];
// u = exp(s - m_tile) packed fp16 pairs: ((blk*32+tile)*16 + i)*256 + t
__device__ uint32_t g_U[512ull * 32 * 16 * 256];

// ---------------- helpers -----------------------------------------------------
__device__ __forceinline__ void split_h2(float a, float b, __half2& h, __half2& l) {
    h = __floats2half2_rn(a, b);
    float2 f = __half22float2(h);
    l = __floats2half2_rn(a - f.x, b - f.y);
}

__device__ __forceinline__ void split_pack(float a, float b, uint32_t& h, uint32_t& l) {
    __half2 hh, ll;
    split_h2(a, b, hh, ll);
    h = *(uint32_t*)&hh;
    l = *(uint32_t*)&ll;
}

__device__ __forceinline__ void mma_f16(float c[4],
                                        uint32_t a0, uint32_t a1, uint32_t a2, uint32_t a3,
                                        uint32_t b0, uint32_t b1) {
    asm volatile(
        "mma.sync.aligned.m16n8k16.row.col.f32.f16.f16.f32 "
        "{%0,%1,%2,%3}, {%4,%5,%6,%7}, {%8,%9}, {%0,%1,%2,%3};"
        : "+f"(c[0]), "+f"(c[1]), "+f"(c[2]), "+f"(c[3])
        : "r"(a0), "r"(a1), "r"(a2), "r"(a3), "r"(b0), "r"(b1));
}

__device__ __forceinline__ uint32_t smem_u32(const void* p) {
    uint32_t a;
    asm("{ .reg .u64 t; cvta.to.shared.u64 t, %1; cvt.u32.u64 %0, t; }"
        : "=r"(a) : "l"(p));
    return a;
}

#define CP_ASYNC16(dst, src) \
    asm volatile("cp.async.cg.shared.global [%0], [%1], 16;" :: "r"(dst), "l"(src))
#define CP_COMMIT() asm volatile("cp.async.commit_group;" ::: "memory")
#define CP_WAIT0()  asm volatile("cp.async.wait_group 0;" ::: "memory")
#define CP_WAIT1()  asm volatile("cp.async.wait_group 1;" ::: "memory")

#define U32AT(p) (*(const uint32_t*)(p))

// ---------------- zero mean_atp -----------------------------------------------
__global__ void zero_atp_kernel(float* __restrict__ atp) {
    int i = blockIdx.x * blockDim.x + threadIdx.x;
    if (i < BB*SS) atp[i] = 0.0f;
}

// ---------------- pre-split fp32 -> hi/lo fp16 --------------------------------
__global__ void split_kernel(const float* __restrict__ src,
                             __half* __restrict__ H, __half* __restrict__ L,
                             int n4) {
    int i = blockIdx.x * blockDim.x + threadIdx.x;
    if (i < n4) {
        float4 v = ((const float4*)src)[i];
        __half2 h01, l01, h23, l23;
        split_h2(v.x, v.y, h01, l01);
        split_h2(v.z, v.w, h23, l23);
        ((__half2*)H)[2*i]   = h01;
        ((__half2*)H)[2*i+1] = h23;
        ((__half2*)L)[2*i]   = l01;
        ((__half2*)L)[2*i+1] = l23;
    }
}

// ---------------- pure-fp16 3-term GEMM, cp.async double-buffered -------------
// BM=BN=128, BK=32, 256 thr (8 warps 2x4), warp 64x32, m16n8k16.
// smem per buf: XH|XL|WH|WL each [128][40] halfs (10240B) -> 40960B; x2 = 81920
#define GK 1024
#define GN 1024
#define LDH 40
#define MAT_B 10240
#define BUF_B 40960
#define GEMM_SMEM 81920
// epilogue modes
#define EP_H16 0
#define EP_VT 1
#define EP_F32 2

__global__ __launch_bounds__(256, 2) void gemm_h16(
    const __half* __restrict__ XH, const __half* __restrict__ XL,
    const __half* __restrict__ WH, const __half* __restrict__ WL,
    const float* __restrict__ bias, int mode,
    __half* __restrict__ YH, __half* __restrict__ YL, float* __restrict__ YF)
{
    extern __shared__ char sm[];
    const uint32_t smb = smem_u32(sm);

    const int t = threadIdx.x;
    const int w = t >> 5;
    const int lane = t & 31;
    const int g = lane >> 2;
    const int tig = lane & 3;
    const int warp_m = (w >> 2) * 64;
    const int warp_n = (w & 3) * 32;
    const int bm = blockIdx.y * 128;
    const int bn = blockIdx.x * 128;

    // chunk mapping: 512 chunks (128 rows x 4) per matrix; this thread: t, t+256
    const int r0c = t >> 2, c0c = t & 3;
    const int r1c = (t + 256) >> 2, c1c = t & 3;   // (t+256)&3 == t&3

    float acc[4][4][4];
#pragma unroll
    for (int mi = 0; mi < 4; ++mi)
#pragma unroll
        for (int ni = 0; ni < 4; ++ni)
#pragma unroll
            for (int j = 0; j < 4; ++j) acc[mi][ni][j] = 0.0f;

    const int NS = GK / 32;

    // stage-issue helper (macro-ish lambda)
    auto issue = [&](int s, int buf) {
        const uint32_t bb = smb + buf * BUF_B;
        const size_t ks = (size_t)s * 32;
        // XH
        CP_ASYNC16(bb + r0c * 80 + c0c * 16,
                   XH + (size_t)(bm + r0c) * GK + ks + c0c * 8);
        CP_ASYNC16(bb + r1c * 80 + c1c * 16,
                   XH + (size_t)(bm + r1c) * GK + ks + c1c * 8);
        // XL
        CP_ASYNC16(bb + MAT_B + r0c * 80 + c0c * 16,
                   XL + (size_t)(bm + r0c) * GK + ks + c0c * 8);
        CP_ASYNC16(bb + MAT_B + r1c * 80 + c1c * 16,
                   XL + (size_t)(bm + r1c) * GK + ks + c1c * 8);
        // WH
        CP_ASYNC16(bb + 2 * MAT_B + r0c * 80 + c0c * 16,
                   WH + (size_t)(bn + r0c) * GK + ks + c0c * 8);
        CP_ASYNC16(bb + 2 * MAT_B + r1c * 80 + c1c * 16,
                   WH + (size_t)(bn + r1c) * GK + ks + c1c * 8);
        // WL
        CP_ASYNC16(bb + 3 * MAT_B + r0c * 80 + c0c * 16,
                   WL + (size_t)(bn + r0c) * GK + ks + c0c * 8);
        CP_ASYNC16(bb + 3 * MAT_B + r1c * 80 + c1c * 16,
                   WL + (size_t)(bn + r1c) * GK + ks + c1c * 8);
    };

    issue(0, 0);
    CP_COMMIT();

    for (int s = 0; s < NS; ++s) {
        const int buf = s & 1;
        __syncthreads();              // all warps done reading buf^1 (prev stage)
        if (s + 1 < NS) {
            issue(s + 1, buf ^ 1);
            CP_COMMIT();
            CP_WAIT1();
        } else {
            CP_WAIT0();
        }
        __syncthreads();              // stage-s data visible to all

        const __half* xh = (const __half*)(sm + buf * BUF_B);
        const __half* xl = (const __half*)(sm + buf * BUF_B + MAT_B);
        const __half* wh = (const __half*)(sm + buf * BUF_B + 2 * MAT_B);
        const __half* wl = (const __half*)(sm + buf * BUF_B + 3 * MAT_B);

#pragma unroll
        for (int k16 = 0; k16 < 2; ++k16) {
            const int k0 = k16 * 16;
            uint32_t bh[4][2], bl[4][2];
#pragma unroll
            for (int ni = 0; ni < 4; ++ni) {
                const int r = warp_n + ni * 8 + g;
                bh[ni][0] = U32AT(&wh[r * LDH + k0 + 2 * tig]);
                bh[ni][1] = U32AT(&wh[r * LDH + k0 + 8 + 2 * tig]);
                bl[ni][0] = U32AT(&wl[r * LDH + k0 + 2 * tig]);
                bl[ni][1] = U32AT(&wl[r * LDH + k0 + 8 + 2 * tig]);
            }
#pragma unroll
            for (int mi = 0; mi < 4; ++mi) {
                const int r0 = warp_m + mi * 16;
                uint32_t ah[4], al[4];
                ah[0] = U32AT(&xh[(r0 + g)     * LDH + k0 + 2 * tig]);
                ah[1] = U32AT(&xh[(r0 + g + 8) * LDH + k0 + 2 * tig]);
                ah[2] = U32AT(&xh[(r0 + g)     * LDH + k0 + 8 + 2 * tig]);
                ah[3] = U32AT(&xh[(r0 + g + 8) * LDH + k0 + 8 + 2 * tig]);
                al[0] = U32AT(&xl[(r0 + g)     * LDH + k0 + 2 * tig]);
                al[1] = U32AT(&xl[(r0 + g + 8) * LDH + k0 + 2 * tig]);
                al[2] = U32AT(&xl[(r0 + g)     * LDH + k0 + 8 + 2 * tig]);
                al[3] = U32AT(&xl[(r0 + g + 8) * LDH + k0 + 8 + 2 * tig]);
#pragma unroll
                for (int ni = 0; ni < 4; ++ni) {
                    mma_f16(acc[mi][ni], ah[0], ah[1], ah[2], ah[3], bh[ni][0], bh[ni][1]);
                    mma_f16(acc[mi][ni], ah[0], ah[1], ah[2], ah[3], bl[ni][0], bl[ni][1]);
                    mma_f16(acc[mi][ni], al[0], al[1], al[2], al[3], bh[ni][0], bh[ni][1]);
                }
            }
        }
    }

    // ---- epilogue ----
#pragma unroll
    for (int ni = 0; ni < 4; ++ni) {
        const int n = bn + warp_n + ni * 8 + 2 * tig;
        const float2 b2 = *(const float2*)(bias + n);
#pragma unroll
        for (int mi = 0; mi < 4; ++mi) {
            const int r0 = bm + warp_m + mi * 16;
            float c0 = acc[mi][ni][0] + b2.x, c1 = acc[mi][ni][1] + b2.y;
            float c2 = acc[mi][ni][2] + b2.x, c3 = acc[mi][ni][3] + b2.y;
            if (mode == EP_F32) {
                *(float2*)(YF + (size_t)(r0 + g) * GN + n)     = make_float2(c0, c1);
                *(float2*)(YF + (size_t)(r0 + g + 8) * GN + n) = make_float2(c2, c3);
            } else if (mode == EP_H16) {
                __half2 h01, l01, h23, l23;
                split_h2(c0, c1, h01, l01);
                split_h2(c2, c3, h23, l23);
                *(__half2*)(YH + (size_t)(r0 + g) * GN + n)     = h01;
                *(__half2*)(YL + (size_t)(r0 + g) * GN + n)     = l01;
                *(__half2*)(YH + (size_t)(r0 + g + 8) * GN + n) = h23;
                *(__half2*)(YL + (size_t)(r0 + g + 8) * GN + n) = l23;
            } else {   // EP_VT: transposed store [b*1024+n][2048]
                __half2 h01, l01, h23, l23;
                split_h2(c0, c1, h01, l01);
                split_h2(c2, c3, h23, l23);
                const int m0r = r0 + g, m1r = r0 + g + 8;
                const size_t a00 = ((size_t)((m0r >> 11) * 1024 + n))     * 2048 + (m0r & 2047);
                const size_t a01 = ((size_t)((m0r >> 11) * 1024 + n + 1)) * 2048 + (m0r & 2047);
                const size_t a10 = ((size_t)((m1r >> 11) * 1024 + n))     * 2048 + (m1r & 2047);
                const size_t a11 = ((size_t)((m1r >> 11) * 1024 + n + 1)) * 2048 + (m1r & 2047);
                YH[a00] = __low2half(h01);  YL[a00] = __low2half(l01);
                YH[a01] = __high2half(h01); YL[a01] = __high2half(l01);
                YH[a10] = __low2half(h23);  YL[a10] = __low2half(l23);
                YH[a11] = __high2half(h23); YL[a11] = __high2half(l23);
            }
        }
    }
}

// ---------------- fused flash attention (fp16 pre-split inputs) ---------------
// smem halfs stride 88 (176B rows, conflict-free frag loads).
// KH@0 KL@11264 VtH@22528 VtL@33792 (each 64x88x2B=11264)
// mhist@45056 [32][128] f32 ; red@61440 [8][64] f32 ; total 63488
#define ALD 88
#define AT_SMEM 63488

__global__ __launch_bounds__(256, 2) void attn_fused(float* __restrict__ atp) {
    extern __shared__ char sm[];
    const uint32_t smb = smem_u32(sm);
    __half* KH  = (__half*)sm;
    __half* KL  = (__half*)(sm + 11264);
    __half* VtH = (__half*)(sm + 22528);
    __half* VtL = (__half*)(sm + 33792);
    float* mhist = (float*)(sm + 45056);
    float* red   = (float*)(sm + 61440);

    const int t = threadIdx.x;
    const int w = t >> 5;
    const int lane = t & 31;
    const int g = lane >> 2;
    const int tig = lane & 3;
    const int bh = blockIdx.y;
    const int b = bh >> 4, h = bh & 15;
    const int qt = blockIdx.x;
    const int q0 = qt * 128;
    const int blk = bh * 16 + qt;

    // chunk mapping for tile loads: 512 chunks (64 rows x 8), thread: t, t+256
    const int r0c = t >> 3, c0c = t & 7;
    const int r1c = (t + 256) >> 3, c1c = t & 7;

    // ---- Q fragments: register-resident (load fp16 hi/lo directly) ----
    uint32_t qh[4][4], ql[4][4];
    {
        const size_t rowA = (size_t)(b * SS + q0 + 16 * w + g) * DD + h * DK;
        const size_t rowB = (size_t)(b * SS + q0 + 16 * w + g + 8) * DD + h * DK;
#pragma unroll
        for (int j = 0; j < 4; ++j) {
            qh[j][0] = U32AT(&g_QH[rowA + 16 * j + 2 * tig]);
            qh[j][1] = U32AT(&g_QH[rowB + 16 * j + 2 * tig]);
            qh[j][2] = U32AT(&g_QH[rowA + 16 * j + 8 + 2 * tig]);
            qh[j][3] = U32AT(&g_QH[rowB + 16 * j + 8 + 2 * tig]);
            ql[j][0] = U32AT(&g_QL[rowA + 16 * j + 2 * tig]);
            ql[j][1] = U32AT(&g_QL[rowB + 16 * j + 2 * tig]);
            ql[j][2] = U32AT(&g_QL[rowA + 16 * j + 8 + 2 * tig]);
            ql[j][3] = U32AT(&g_QL[rowB + 16 * j + 8 + 2 * tig]);
        }
    }

    float oacc[8][4];
#pragma unroll
    for (int ni = 0; ni < 8; ++ni)
#pragma unroll
        for (int j = 0; j < 4; ++j) oacc[ni][j] = 0.0f;

    float m0 = -INFINITY, m1 = -INFINITY, l0 = 0.0f, l1 = 0.0f;

    for (int tile = 0; tile < 32; ++tile) {
        __syncthreads();
        // cp.async tile loads: K [token][dk], Vt [dk][token]
        {
            const size_t ksrc0 = (size_t)(b * SS + tile * 64 + r0c) * DD + h * DK + c0c * 8;
            const size_t ksrc1 = (size_t)(b * SS + tile * 64 + r1c) * DD + h * DK + c1c * 8;
            const size_t vsrc0 = (size_t)(b * 1024 + h * 64 + r0c) * 2048 + tile * 64 + c0c * 8;
            const size_t vsrc1 = (size_t)(b * 1024 + h * 64 + r1c) * 2048 + tile * 64 + c1c * 8;
            const uint32_t d0 = r0c * 176 + c0c * 16;
            const uint32_t d1 = r1c * 176 + c1c * 16;
            CP_ASYNC16(smb + d0,         g_KH + ksrc0);
            CP_ASYNC16(smb + d1,         g_KH + ksrc1);
            CP_ASYNC16(smb + 11264 + d0, g_KL + ksrc0);
            CP_ASYNC16(smb + 11264 + d1, g_KL + ksrc1);
            CP_ASYNC16(smb + 22528 + d0, g_VtH + vsrc0);
            CP_ASYNC16(smb + 22528 + d1, g_VtH + vsrc1);
            CP_ASYNC16(smb + 33792 + d0, g_VtL + vsrc0);
            CP_ASYNC16(smb + 33792 + d1, g_VtL + vsrc1);
            CP_COMMIT();
            CP_WAIT0();
        }
        __syncthreads();

        // ---- QK^T ----
        float sacc[8][4];
#pragma unroll
        for (int ni = 0; ni < 8; ++ni)
#pragma unroll
            for (int j = 0; j < 4; ++j) sacc[ni][j] = 0.0f;

#pragma unroll
        for (int j = 0; j < 4; ++j) {
#pragma unroll
            for (int ni = 0; ni < 8; ++ni) {
                const int key = ni * 8 + g;
                uint32_t bh0 = U32AT(&KH[key * ALD + 16 * j + 2 * tig]);
                uint32_t bh1 = U32AT(&KH[key * ALD + 16 * j + 8 + 2 * tig]);
                uint32_t bl0 = U32AT(&KL[key * ALD + 16 * j + 2 * tig]);
                uint32_t bl1 = U32AT(&KL[key * ALD + 16 * j + 8 + 2 * tig]);
                mma_f16(sacc[ni], qh[j][0], qh[j][1], qh[j][2], qh[j][3], bh0, bh1);
                mma_f16(sacc[ni], qh[j][0], qh[j][1], qh[j][2], qh[j][3], bl0, bl1);
                mma_f16(sacc[ni], ql[j][0], ql[j][1], ql[j][2], ql[j][3], bh0, bh1);
            }
        }

        // ---- scale + row max ----
        float mx0 = -INFINITY, mx1 = -INFINITY;
#pragma unroll
        for (int ni = 0; ni < 8; ++ni) {
            sacc[ni][0] *= SCALE; sacc[ni][1] *= SCALE;
            sacc[ni][2] *= SCALE; sacc[ni][3] *= SCALE;
            mx0 = fmaxf(mx0, fmaxf(sacc[ni][0], sacc[ni][1]));
            mx1 = fmaxf(mx1, fmaxf(sacc[ni][2], sacc[ni][3]));
        }
        mx0 = fmaxf(mx0, __shfl_xor_sync(0xffffffffu, mx0, 1));
        mx0 = fmaxf(mx0, __shfl_xor_sync(0xffffffffu, mx0, 2));
        mx1 = fmaxf(mx1, __shfl_xor_sync(0xffffffffu, mx1, 1));
        mx1 = fmaxf(mx1, __shfl_xor_sync(0xffffffffu, mx1, 2));

        const float mn0 = fmaxf(m0, mx0);
        const float mn1 = fmaxf(m1, mx1);
        const float al0 = __expf(m0 - mn0);
        const float al1 = __expf(m1 - mn1);
        m0 = mn0; m1 = mn1;

        // ---- u = exp(s-m); fp16 store to scratch; keep fp32 for PV ----
        const size_t ubase = ((size_t)(blk * 32 + tile) * 16) * 256 + t;
        float ls0 = 0.0f, ls1 = 0.0f;
#pragma unroll
        for (int ni = 0; ni < 8; ++ni) {
            float u0 = __expf(sacc[ni][0] - m0);
            float u1 = __expf(sacc[ni][1] - m0);
            float u2 = __expf(sacc[ni][2] - m1);
            float u3 = __expf(sacc[ni][3] - m1);
            ls0 += u0 + u1; ls1 += u2 + u3;
            __half2 p01 = __floats2half2_rn(u0, u1);
            __half2 p23 = __floats2half2_rn(u2, u3);
            g_U[ubase + (size_t)(2 * ni) * 256]     = *(uint32_t*)&p01;
            g_U[ubase + (size_t)(2 * ni + 1) * 256] = *(uint32_t*)&p23;
            sacc[ni][0] = u0; sacc[ni][1] = u1;
            sacc[ni][2] = u2; sacc[ni][3] = u3;
        }
        l0 = l0 * al0 + ls0;
        l1 = l1 * al1 + ls1;

        if (tig == 0) {
            mhist[tile * 128 + 16 * w + g]     = m0;
            mhist[tile * 128 + 16 * w + g + 8] = m1;
        }

#pragma unroll
        for (int ni = 0; ni < 8; ++ni) {
            oacc[ni][0] *= al0; oacc[ni][1] *= al0;
            oacc[ni][2] *= al1; oacc[ni][3] *= al1;
        }

        // ---- PV ----
#pragma unroll
        for (int j = 0; j < 4; ++j) {
            uint32_t ah0, ah1, ah2, ah3, aL0, aL1, aL2, aL3;
            split_pack(sacc[2*j][0],   sacc[2*j][1],   ah0, aL0);
            split_pack(sacc[2*j][2],   sacc[2*j][3],   ah1, aL1);
            split_pack(sacc[2*j+1][0], sacc[2*j+1][1], ah2, aL2);
            split_pack(sacc[2*j+1][2], sacc[2*j+1][3], ah3, aL3);
#pragma unroll
            for (int ni = 0; ni < 8; ++ni) {
                const int dk = ni * 8 + g;
                uint32_t bh0 = U32AT(&VtH[dk * ALD + 16 * j + 2 * tig]);
                uint32_t bh1 = U32AT(&VtH[dk * ALD + 16 * j + 8 + 2 * tig]);
                uint32_t bl0 = U32AT(&VtL[dk * ALD + 16 * j + 2 * tig]);
                uint32_t bl1 = U32AT(&VtL[dk * ALD + 16 * j + 8 + 2 * tig]);
                mma_f16(oacc[ni], ah0, ah1, ah2, ah3, bh0, bh1);
                mma_f16(oacc[ni], ah0, ah1, ah2, ah3, bl0, bl1);
                mma_f16(oacc[ni], aL0, aL1, aL2, aL3, bh0, bh1);
            }
        }
    }

    // ---- finalize: merge l, write C as split fp16 ----
    l0 += __shfl_xor_sync(0xffffffffu, l0, 1);
    l0 += __shfl_xor_sync(0xffffffffu, l0, 2);
    l1 += __shfl_xor_sync(0xffffffffu, l1, 1);
    l1 += __shfl_xor_sync(0xffffffffu, l1, 2);
    const float il0 = 1.0f / l0;
    const float il1 = 1.0f / l1;

    {
        const size_t rowA = (size_t)(b * SS + q0 + 16 * w + g) * DD + h * DK;
        const size_t rowB = (size_t)(b * SS + q0 + 16 * w + g + 8) * DD + h * DK;
#pragma unroll
        for (int ni = 0; ni < 8; ++ni) {
            const int col = ni * 8 + 2 * tig;
            __half2 hA, lA, hB, lB;
            split_h2(oacc[ni][0] * il0, oacc[ni][1] * il0, hA, lA);
            split_h2(oacc[ni][2] * il1, oacc[ni][3] * il1, hB, lB);
            *(__half2*)&g_CH[rowA + col] = hA;
            *(__half2*)&g_CL[rowA + col] = lA;
            *(__half2*)&g_CH[rowB + col] = hB;
            *(__half2*)&g_CL[rowB + col] = lB;
        }
    }

    __syncthreads();

    // ---- colsum readback ----
    for (int tile = 0; tile < 32; ++tile) {
        const size_t ubase = ((size_t)(blk * 32 + tile) * 16) * 256 + t;
        uint32_t uu[16];
#pragma unroll
        for (int i = 0; i < 16; ++i)
            uu[i] = g_U[ubase + (size_t)i * 256];
        const float w0 = __expf(mhist[tile * 128 + 16 * w + g]     - m0) * il0;
        const float w1 = __expf(mhist[tile * 128 + 16 * w + g + 8] - m1) * il1;

#pragma unroll
        for (int ni = 0; ni < 8; ++ni) {
            float2 fa = __half22float2(*(__half2*)&uu[2 * ni]);
            float2 fb = __half22float2(*(__half2*)&uu[2 * ni + 1]);
            float cs0 = fa.x * w0 + fb.x * w1;
            float cs1 = fa.y * w0 + fb.y * w1;
            cs0 += __shfl_xor_sync(0xffffffffu, cs0, 4);
            cs0 += __shfl_xor_sync(0xffffffffu, cs0, 8);
            cs0 += __shfl_xor_sync(0xffffffffu, cs0, 16);
            cs1 += __shfl_xor_sync(0xffffffffu, cs1, 4);
            cs1 += __shfl_xor_sync(0xffffffffu, cs1, 8);
            cs1 += __shfl_xor_sync(0xffffffffu, cs1, 16);
            if (lane < 4) {
                red[w * 64 + ni * 8 + 2 * tig]     = cs0;
                red[w * 64 + ni * 8 + 2 * tig + 1] = cs1;
            }
        }
        __syncthreads();
        if (t < 64) {
            float s = 0.0f;
#pragma unroll
            for (int wi = 0; wi < 8; ++wi) s += red[wi * 64 + t];
            atomicAdd(&atp[b * SS + tile * 64 + t], s * INV_HS);
        }
        __syncthreads();
    }
}

// ---------------- launch ------------------------------------------------------
extern "C" void kernel_launch(void* const* d_in, const int* in_sizes, int n_in,
                              void* d_out, int out_size) {
    (void)in_sizes; (void)n_in; (void)out_size;
    const float* query = (const float*)d_in[0];
    const float* key   = (const float*)d_in[1];
    const float* value = (const float*)d_in[2];
    const float* Wq = (const float*)d_in[3];
    const float* bq = (const float*)d_in[4];
    const float* Wk = (const float*)d_in[5];
    const float* bk = (const float*)d_in[6];
    const float* Wv = (const float*)d_in[7];
    const float* bv = (const float*)d_in[8];
    const float* Wo = (const float*)d_in[9];
    const float* bo = (const float*)d_in[10];

    float* out = (float*)d_out;
    float* atp = out + (size_t)BB * SS * DD;

    __half *inH, *inL, *QH, *QL, *KH, *KL, *VtH, *VtL, *CH, *CL;
    cudaGetSymbolAddress((void**)&inH, g_inH);
    cudaGetSymbolAddress((void**)&inL, g_inL);
    cudaGetSymbolAddress((void**)&QH, g_QH);
    cudaGetSymbolAddress((void**)&QL, g_QL);
    cudaGetSymbolAddress((void**)&KH, g_KH);
    cudaGetSymbolAddress((void**)&KL, g_KL);
    cudaGetSymbolAddress((void**)&VtH, g_VtH);
    cudaGetSymbolAddress((void**)&VtL, g_VtL);
    cudaGetSymbolAddress((void**)&CH, g_CH);
    cudaGetSymbolAddress((void**)&CL, g_CL);

    zero_atp_kernel<<<(BB*SS + 255) / 256, 256>>>(atp);

    // pre-split inputs & weights
    const int NX4 = MTOT * DD / 4;          // 1048576
    const int NW4 = DD * DD / 4;            // 262144
    const size_t oQ = 0, oK = 4194304, oV = 8388608;
    const size_t oWq = 12582912, oWk = 13631488, oWv = 14680064, oWo = 15728640;
    split_kernel<<<NX4 / 256, 256>>>(query, inH + oQ,  inL + oQ,  NX4);
    split_kernel<<<NX4 / 256, 256>>>(key,   inH + oK,  inL + oK,  NX4);
    split_kernel<<<NX4 / 256, 256>>>(value, inH + oV,  inL + oV,  NX4);
    split_kernel<<<NW4 / 256, 256>>>(Wq, inH + oWq, inL + oWq, NW4);
    split_kernel<<<NW4 / 256, 256>>>(Wk, inH + oWk, inL + oWk, NW4);
    split_kernel<<<NW4 / 256, 256>>>(Wv, inH + oWv, inL + oWv, NW4);
    split_kernel<<<NW4 / 256, 256>>>(Wo, inH + oWo, inL + oWo, NW4);

    cudaFuncSetAttribute(gemm_h16, cudaFuncAttributeMaxDynamicSharedMemorySize,
                         GEMM_SMEM);
    cudaFuncSetAttribute(attn_fused, cudaFuncAttributeMaxDynamicSharedMemorySize,
                         AT_SMEM);

    dim3 gg(GN / 128, MTOT / 128);
    gemm_h16<<<gg, 256, GEMM_SMEM>>>(inH + oQ, inL + oQ, inH + oWq, inL + oWq,
                                     bq, EP_H16, QH, QL, nullptr);
    gemm_h16<<<gg, 256, GEMM_SMEM>>>(inH + oK, inL + oK, inH + oWk, inL + oWk,
                                     bk, EP_H16, KH, KL, nullptr);
    gemm_h16<<<gg, 256, GEMM_SMEM>>>(inH + oV, inL + oV, inH + oWv, inL + oWv,
                                     bv, EP_VT, VtH, VtL, nullptr);

    attn_fused<<<dim3(16, 32), 256, AT_SMEM>>>(atp);

    gemm_h16<<<gg, 256, GEMM_SMEM>>>(CH, CL, inH + oWo, inL + oWo,
                                     bo, EP_F32, nullptr, nullptr, out);
}

// round 10
// speedup vs baseline: 1.5714x; 1.0917x over previous
#include <cuda_runtime.h>
#include <cuda_fp16.h>
#include <math.h>
#include <stdint.h>

#define BB 2
#define SS 2048
#define DD 1024
#define HH 16
#define DK 64
#define MTOT (BB*SS)

#define SCALE 12.5f                  // 100/sqrt(64)
#define INV_HS (1.0f/32768.0f)       // 1/(H*S)

// ---------------- device scratch ----------------------------------------------
__device__ __half g_inH[16777216];
__device__ __half g_inL[16777216];
__device__ __half g_QH[4194304], g_QL[4194304];
__device__ __half g_KH[4194304], g_KL[4194304];
__device__ __half g_VtH[4194304], g_VtL[4194304];   // [b*1024+n][2048] transposed
__device__ __half g_CH[4194304], g_CL[4194304];
// u scratch, uint4-chunked: chunk c of (blk,tile) at ((blk*32+tile)*4 + c)*256 + t
__device__ uint32_t g_U[512ull * 32 * 16 * 256];

// ---------------- helpers -----------------------------------------------------
__device__ __forceinline__ void split_h2(float a, float b, __half2& h, __half2& l) {
    h = __floats2half2_rn(a, b);
    float2 f = __half22float2(h);
    l = __floats2half2_rn(a - f.x, b - f.y);
}

__device__ __forceinline__ void split_pack(float a, float b, uint32_t& h, uint32_t& l) {
    __half2 hh, ll;
    split_h2(a, b, hh, ll);
    h = *(uint32_t*)&hh;
    l = *(uint32_t*)&ll;
}

__device__ __forceinline__ void mma_f16(float c[4],
                                        uint32_t a0, uint32_t a1, uint32_t a2, uint32_t a3,
                                        uint32_t b0, uint32_t b1) {
    asm volatile(
        "mma.sync.aligned.m16n8k16.row.col.f32.f16.f16.f32 "
        "{%0,%1,%2,%3}, {%4,%5,%6,%7}, {%8,%9}, {%0,%1,%2,%3};"
        : "+f"(c[0]), "+f"(c[1]), "+f"(c[2]), "+f"(c[3])
        : "r"(a0), "r"(a1), "r"(a2), "r"(a3), "r"(b0), "r"(b1));
}

__device__ __forceinline__ void ldsm_x4(uint32_t& r0, uint32_t& r1,
                                        uint32_t& r2, uint32_t& r3, uint32_t addr) {
    asm volatile("ldmatrix.sync.aligned.m8n8.x4.shared.b16 {%0,%1,%2,%3}, [%4];"
        : "=r"(r0), "=r"(r1), "=r"(r2), "=r"(r3) : "r"(addr));
}

__device__ __forceinline__ uint32_t smem_u32(const void* p) {
    uint32_t a;
    asm("{ .reg .u64 t; cvta.to.shared.u64 t, %1; cvt.u32.u64 %0, t; }"
        : "=r"(a) : "l"(p));
    return a;
}

#define CP_ASYNC16(dst, src) \
    asm volatile("cp.async.cg.shared.global [%0], [%1], 16;" :: "r"(dst), "l"(src))
#define CP_COMMIT() asm volatile("cp.async.commit_group;" ::: "memory")
#define CP_WAIT0()  asm volatile("cp.async.wait_group 0;" ::: "memory")

// ---------------- zero mean_atp -----------------------------------------------
__global__ void zero_atp_kernel(float* __restrict__ atp) {
    int i = blockIdx.x * blockDim.x + threadIdx.x;
    if (i < BB*SS) atp[i] = 0.0f;
}

// ---------------- pre-split fp32 -> hi/lo fp16 --------------------------------
__global__ void split_kernel(const float* __restrict__ src,
                             __half* __restrict__ H, __half* __restrict__ L,
                             int n4) {
    int i = blockIdx.x * blockDim.x + threadIdx.x;
    if (i < n4) {
        float4 v = ((const float4*)src)[i];
        __half2 h01, l01, h23, l23;
        split_h2(v.x, v.y, h01, l01);
        split_h2(v.z, v.w, h23, l23);
        ((__half2*)H)[2*i]   = h01;
        ((__half2*)H)[2*i+1] = h23;
        ((__half2*)L)[2*i]   = l01;
        ((__half2*)L)[2*i+1] = l23;
    }
}

// ---------------- pure-fp16 3-term GEMM, cp.async + ldmatrix ------------------
#define GK 1024
#define GN 1024
#define LDH 40
#define MAT_B 10240
#define BUF_B 40960
#define GEMM_SMEM 81920
#define EP_H16 0
#define EP_VT 1
#define EP_F32 2

__global__ __launch_bounds__(256, 2) void gemm_h16(
    const __half* __restrict__ XH, const __half* __restrict__ XL,
    const __half* __restrict__ WH, const __half* __restrict__ WL,
    const float* __restrict__ bias, int mode,
    __half* __restrict__ YH, __half* __restrict__ YL, float* __restrict__ YF)
{
    extern __shared__ char sm[];
    const uint32_t smb = smem_u32(sm);

    const int t = threadIdx.x;
    const int w = t >> 5;
    const int lane = t & 31;
    const int g = lane >> 2;
    const int tig = lane & 3;
    const int warp_m = (w >> 2) * 64;
    const int warp_n = (w & 3) * 32;
    const int bm = blockIdx.y * 128;
    const int bn = blockIdx.x * 128;

    // ldmatrix lane coordinates
    const int arow = lane & 15;               // A: row offset
    const int acol = (lane >> 4) * 8;         // A: col offset
    const int brow = (lane & 7) + ((lane >> 4) << 3);   // B: row offset
    const int bcol = ((lane >> 3) & 1) * 8;             // B: col offset

    // cp.async chunk mapping: thread covers chunks t and t+256 (128 rows x 4 chunks)
    const int r0c = t >> 2, c0c = t & 3;
    const int r1c = (t + 256) >> 2;

    float acc[4][4][4];
#pragma unroll
    for (int mi = 0; mi < 4; ++mi)
#pragma unroll
        for (int ni = 0; ni < 4; ++ni)
#pragma unroll
            for (int j = 0; j < 4; ++j) acc[mi][ni][j] = 0.0f;

    const int NS = GK / 32;

    auto issue = [&](int s, int buf) {
        const uint32_t bb = smb + buf * BUF_B;
        const size_t ks = (size_t)s * 32;
        CP_ASYNC16(bb + r0c * 80 + c0c * 16, XH + (size_t)(bm + r0c) * GK + ks + c0c * 8);
        CP_ASYNC16(bb + r1c * 80 + c0c * 16, XH + (size_t)(bm + r1c) * GK + ks + c0c * 8);
        CP_ASYNC16(bb + MAT_B + r0c * 80 + c0c * 16, XL + (size_t)(bm + r0c) * GK + ks + c0c * 8);
        CP_ASYNC16(bb + MAT_B + r1c * 80 + c0c * 16, XL + (size_t)(bm + r1c) * GK + ks + c0c * 8);
        CP_ASYNC16(bb + 2 * MAT_B + r0c * 80 + c0c * 16, WH + (size_t)(bn + r0c) * GK + ks + c0c * 8);
        CP_ASYNC16(bb + 2 * MAT_B + r1c * 80 + c0c * 16, WH + (size_t)(bn + r1c) * GK + ks + c0c * 8);
        CP_ASYNC16(bb + 3 * MAT_B + r0c * 80 + c0c * 16, WL + (size_t)(bn + r0c) * GK + ks + c0c * 8);
        CP_ASYNC16(bb + 3 * MAT_B + r1c * 80 + c0c * 16, WL + (size_t)(bn + r1c) * GK + ks + c0c * 8);
    };

    issue(0, 0);
    CP_COMMIT();

    for (int s = 0; s < NS; ++s) {
        const int buf = s & 1;
        CP_WAIT0();
        __syncthreads();
        if (s + 1 < NS) {
            issue(s + 1, buf ^ 1);
            CP_COMMIT();
        }

        const uint32_t xb = smb + buf * BUF_B;
        const uint32_t wb = xb + 2 * MAT_B;

#pragma unroll
        for (int k16 = 0; k16 < 2; ++k16) {
            const int k0 = k16 * 16;
            uint32_t bh[4][2], bl[4][2];
#pragma unroll
            for (int p = 0; p < 2; ++p) {
                const uint32_t addr = wb + ((warp_n + p * 16 + brow) * LDH + k0 + bcol) * 2;
                ldsm_x4(bh[2*p][0], bh[2*p][1], bh[2*p+1][0], bh[2*p+1][1], addr);
                ldsm_x4(bl[2*p][0], bl[2*p][1], bl[2*p+1][0], bl[2*p+1][1], addr + MAT_B);
            }
#pragma unroll
            for (int mi = 0; mi < 4; ++mi) {
                const uint32_t addrA = xb + ((warp_m + mi * 16 + arow) * LDH + k0 + acol) * 2;
                uint32_t ah[4], al[4];
                ldsm_x4(ah[0], ah[1], ah[2], ah[3], addrA);
                ldsm_x4(al[0], al[1], al[2], al[3], addrA + MAT_B);
#pragma unroll
                for (int ni = 0; ni < 4; ++ni) {
                    mma_f16(acc[mi][ni], ah[0], ah[1], ah[2], ah[3], bh[ni][0], bh[ni][1]);
                    mma_f16(acc[mi][ni], ah[0], ah[1], ah[2], ah[3], bl[ni][0], bl[ni][1]);
                    mma_f16(acc[mi][ni], al[0], al[1], al[2], al[3], bh[ni][0], bh[ni][1]);
                }
            }
        }
        __syncthreads();
    }

    // ---- epilogue ----
#pragma unroll
    for (int ni = 0; ni < 4; ++ni) {
        const int n = bn + warp_n + ni * 8 + 2 * tig;
        const float2 b2 = *(const float2*)(bias + n);
#pragma unroll
        for (int mi = 0; mi < 4; ++mi) {
            const int r0 = bm + warp_m + mi * 16;
            float c0 = acc[mi][ni][0] + b2.x, c1 = acc[mi][ni][1] + b2.y;
            float c2 = acc[mi][ni][2] + b2.x, c3 = acc[mi][ni][3] + b2.y;
            if (mode == EP_F32) {
                *(float2*)(YF + (size_t)(r0 + g) * GN + n)     = make_float2(c0, c1);
                *(float2*)(YF + (size_t)(r0 + g + 8) * GN + n) = make_float2(c2, c3);
            } else if (mode == EP_H16) {
                __half2 h01, l01, h23, l23;
                split_h2(c0, c1, h01, l01);
                split_h2(c2, c3, h23, l23);
                *(__half2*)(YH + (size_t)(r0 + g) * GN + n)     = h01;
                *(__half2*)(YL + (size_t)(r0 + g) * GN + n)     = l01;
                *(__half2*)(YH + (size_t)(r0 + g + 8) * GN + n) = h23;
                *(__half2*)(YL + (size_t)(r0 + g + 8) * GN + n) = l23;
            } else {   // EP_VT
                __half2 h01, l01, h23, l23;
                split_h2(c0, c1, h01, l01);
                split_h2(c2, c3, h23, l23);
                const int m0r = r0 + g, m1r = r0 + g + 8;
                const size_t a00 = ((size_t)((m0r >> 11) * 1024 + n))     * 2048 + (m0r & 2047);
                const size_t a01 = ((size_t)((m0r >> 11) * 1024 + n + 1)) * 2048 + (m0r & 2047);
                const size_t a10 = ((size_t)((m1r >> 11) * 1024 + n))     * 2048 + (m1r & 2047);
                const size_t a11 = ((size_t)((m1r >> 11) * 1024 + n + 1)) * 2048 + (m1r & 2047);
                YH[a00] = __low2half(h01);  YL[a00] = __low2half(l01);
                YH[a01] = __high2half(h01); YL[a01] = __high2half(l01);
                YH[a10] = __low2half(h23);  YL[a10] = __low2half(l23);
                YH[a11] = __high2half(h23); YL[a11] = __high2half(l23);
            }
        }
    }
}

// ---------------- fused flash attention: double-buffered + ldmatrix -----------
// smem: buf0@0, buf1@45056 (each: KH 11264 | KL 11264 | VtH 11264 | VtL 11264)
//       mhist@90112 [32][128] f32 ; red@106496 [8][64] f32 ; total 108544
#define ALD 88
#define ABUF 45056
#define AT_SMEM 108544

__global__ __launch_bounds__(256, 2) void attn_fused(float* __restrict__ atp) {
    extern __shared__ char sm[];
    const uint32_t smb = smem_u32(sm);
    float* mhist = (float*)(sm + 90112);
    float* red   = (float*)(sm + 106496);

    const int t = threadIdx.x;
    const int w = t >> 5;
    const int lane = t & 31;
    const int g = lane >> 2;
    const int tig = lane & 3;
    const int bh = blockIdx.y;
    const int b = bh >> 4, h = bh & 15;
    const int qt = blockIdx.x;
    const int q0 = qt * 128;
    const int blk = bh * 16 + qt;

    const int brow = (lane & 7) + ((lane >> 4) << 3);
    const int bcol = ((lane >> 3) & 1) * 8;

    // cp.async chunk mapping: 64 rows x 8 chunks; thread covers t and t+256
    const int r0c = t >> 3, c0c = t & 7;
    const int r1c = (t + 256) >> 3;

    // ---- Q fragments: register-resident ----
    uint32_t qh[4][4], ql[4][4];
    {
        const size_t rowA = (size_t)(b * SS + q0 + 16 * w + g) * DD + h * DK;
        const size_t rowB = (size_t)(b * SS + q0 + 16 * w + g + 8) * DD + h * DK;
#pragma unroll
        for (int j = 0; j < 4; ++j) {
            qh[j][0] = *(const uint32_t*)&g_QH[rowA + 16 * j + 2 * tig];
            qh[j][1] = *(const uint32_t*)&g_QH[rowB + 16 * j + 2 * tig];
            qh[j][2] = *(const uint32_t*)&g_QH[rowA + 16 * j + 8 + 2 * tig];
            qh[j][3] = *(const uint32_t*)&g_QH[rowB + 16 * j + 8 + 2 * tig];
            ql[j][0] = *(const uint32_t*)&g_QL[rowA + 16 * j + 2 * tig];
            ql[j][1] = *(const uint32_t*)&g_QL[rowB + 16 * j + 2 * tig];
            ql[j][2] = *(const uint32_t*)&g_QL[rowA + 16 * j + 8 + 2 * tig];
            ql[j][3] = *(const uint32_t*)&g_QL[rowB + 16 * j + 8 + 2 * tig];
        }
    }

    auto issueT = [&](int tile, int buf) {
        const uint32_t bb = smb + buf * ABUF;
        const size_t ksrc0 = (size_t)(b * SS + tile * 64 + r0c) * DD + h * DK + c0c * 8;
        const size_t ksrc1 = (size_t)(b * SS + tile * 64 + r1c) * DD + h * DK + c0c * 8;
        const size_t vsrc0 = (size_t)(b * 1024 + h * 64 + r0c) * 2048 + tile * 64 + c0c * 8;
        const size_t vsrc1 = (size_t)(b * 1024 + h * 64 + r1c) * 2048 + tile * 64 + c0c * 8;
        const uint32_t d0 = r0c * 176 + c0c * 16;
        const uint32_t d1 = r1c * 176 + c0c * 16;
        CP_ASYNC16(bb + d0,         g_KH + ksrc0);
        CP_ASYNC16(bb + d1,         g_KH + ksrc1);
        CP_ASYNC16(bb + 11264 + d0, g_KL + ksrc0);
        CP_ASYNC16(bb + 11264 + d1, g_KL + ksrc1);
        CP_ASYNC16(bb + 22528 + d0, g_VtH + vsrc0);
        CP_ASYNC16(bb + 22528 + d1, g_VtH + vsrc1);
        CP_ASYNC16(bb + 33792 + d0, g_VtL + vsrc0);
        CP_ASYNC16(bb + 33792 + d1, g_VtL + vsrc1);
    };

    float oacc[8][4];
#pragma unroll
    for (int ni = 0; ni < 8; ++ni)
#pragma unroll
        for (int j = 0; j < 4; ++j) oacc[ni][j] = 0.0f;

    float m0 = -INFINITY, m1 = -INFINITY, l0 = 0.0f, l1 = 0.0f;

    issueT(0, 0);
    CP_COMMIT();

    for (int tile = 0; tile < 32; ++tile) {
        const int buf = tile & 1;
        CP_WAIT0();
        __syncthreads();
        if (tile + 1 < 32) {
            issueT(tile + 1, buf ^ 1);
            CP_COMMIT();
        }
        const uint32_t bb = smb + buf * ABUF;

        // ---- QK^T via ldmatrix ----
        float sacc[8][4];
#pragma unroll
        for (int ni = 0; ni < 8; ++ni)
#pragma unroll
            for (int j = 0; j < 4; ++j) sacc[ni][j] = 0.0f;

#pragma unroll
        for (int j = 0; j < 4; ++j) {
            const int k0 = 16 * j;
#pragma unroll
            for (int p = 0; p < 4; ++p) {
                const uint32_t addr = bb + ((p * 16 + brow) * ALD + k0 + bcol) * 2;
                uint32_t b0, b1, b2, b3, c0, c1, c2, c3;
                ldsm_x4(b0, b1, b2, b3, addr);
                ldsm_x4(c0, c1, c2, c3, addr + 11264);
                mma_f16(sacc[2*p],   qh[j][0], qh[j][1], qh[j][2], qh[j][3], b0, b1);
                mma_f16(sacc[2*p],   qh[j][0], qh[j][1], qh[j][2], qh[j][3], c0, c1);
                mma_f16(sacc[2*p],   ql[j][0], ql[j][1], ql[j][2], ql[j][3], b0, b1);
                mma_f16(sacc[2*p+1], qh[j][0], qh[j][1], qh[j][2], qh[j][3], b2, b3);
                mma_f16(sacc[2*p+1], qh[j][0], qh[j][1], qh[j][2], qh[j][3], c2, c3);
                mma_f16(sacc[2*p+1], ql[j][0], ql[j][1], ql[j][2], ql[j][3], b2, b3);
            }
        }

        // ---- scale + row max ----
        float mx0 = -INFINITY, mx1 = -INFINITY;
#pragma unroll
        for (int ni = 0; ni < 8; ++ni) {
            sacc[ni][0] *= SCALE; sacc[ni][1] *= SCALE;
            sacc[ni][2] *= SCALE; sacc[ni][3] *= SCALE;
            mx0 = fmaxf(mx0, fmaxf(sacc[ni][0], sacc[ni][1]));
            mx1 = fmaxf(mx1, fmaxf(sacc[ni][2], sacc[ni][3]));
        }
        mx0 = fmaxf(mx0, __shfl_xor_sync(0xffffffffu, mx0, 1));
        mx0 = fmaxf(mx0, __shfl_xor_sync(0xffffffffu, mx0, 2));
        mx1 = fmaxf(mx1, __shfl_xor_sync(0xffffffffu, mx1, 1));
        mx1 = fmaxf(mx1, __shfl_xor_sync(0xffffffffu, mx1, 2));

        const float mn0 = fmaxf(m0, mx0);
        const float mn1 = fmaxf(m1, mx1);
        const float al0 = __expf(m0 - mn0);
        const float al1 = __expf(m1 - mn1);
        m0 = mn0; m1 = mn1;

        // ---- u = exp(s-m); STG.128 to scratch; keep fp32 for PV ----
        uint4* U4 = (uint4*)g_U + ((size_t)(blk * 32 + tile) * 4) * 256 + t;
        float ls0 = 0.0f, ls1 = 0.0f;
        uint32_t prev01 = 0, prev23 = 0;
#pragma unroll
        for (int ni = 0; ni < 8; ++ni) {
            float u0 = __expf(sacc[ni][0] - m0);
            float u1 = __expf(sacc[ni][1] - m0);
            float u2 = __expf(sacc[ni][2] - m1);
            float u3 = __expf(sacc[ni][3] - m1);
            ls0 += u0 + u1; ls1 += u2 + u3;
            __half2 p01 = __floats2half2_rn(u0, u1);
            __half2 p23 = __floats2half2_rn(u2, u3);
            if (ni & 1) {
                U4[(ni >> 1) * 256] = make_uint4(prev01, prev23,
                                                 *(uint32_t*)&p01, *(uint32_t*)&p23);
            } else {
                prev01 = *(uint32_t*)&p01;
                prev23 = *(uint32_t*)&p23;
            }
            sacc[ni][0] = u0; sacc[ni][1] = u1;
            sacc[ni][2] = u2; sacc[ni][3] = u3;
        }
        l0 = l0 * al0 + ls0;
        l1 = l1 * al1 + ls1;

        if (tig == 0) {
            mhist[tile * 128 + 16 * w + g]     = m0;
            mhist[tile * 128 + 16 * w + g + 8] = m1;
        }

#pragma unroll
        for (int ni = 0; ni < 8; ++ni) {
            oacc[ni][0] *= al0; oacc[ni][1] *= al0;
            oacc[ni][2] *= al1; oacc[ni][3] *= al1;
        }

        // ---- PV via ldmatrix ----
#pragma unroll
        for (int j = 0; j < 4; ++j) {
            uint32_t ah0, ah1, ah2, ah3, aL0, aL1, aL2, aL3;
            split_pack(sacc[2*j][0],   sacc[2*j][1],   ah0, aL0);
            split_pack(sacc[2*j][2],   sacc[2*j][3],   ah1, aL1);
            split_pack(sacc[2*j+1][0], sacc[2*j+1][1], ah2, aL2);
            split_pack(sacc[2*j+1][2], sacc[2*j+1][3], ah3, aL3);
            const int k0 = 16 * j;
#pragma unroll
            for (int p = 0; p < 4; ++p) {
                const uint32_t addr = bb + 22528 + ((p * 16 + brow) * ALD + k0 + bcol) * 2;
                uint32_t b0, b1, b2, b3, c0, c1, c2, c3;
                ldsm_x4(b0, b1, b2, b3, addr);
                ldsm_x4(c0, c1, c2, c3, addr + 11264);
                mma_f16(oacc[2*p],   ah0, ah1, ah2, ah3, b0, b1);
                mma_f16(oacc[2*p],   ah0, ah1, ah2, ah3, c0, c1);
                mma_f16(oacc[2*p],   aL0, aL1, aL2, aL3, b0, b1);
                mma_f16(oacc[2*p+1], ah0, ah1, ah2, ah3, b2, b3);
                mma_f16(oacc[2*p+1], ah0, ah1, ah2, ah3, c2, c3);
                mma_f16(oacc[2*p+1], aL0, aL1, aL2, aL3, b2, b3);
            }
        }
        __syncthreads();
    }

    // ---- finalize: merge l, write C split fp16 ----
    l0 += __shfl_xor_sync(0xffffffffu, l0, 1);
    l0 += __shfl_xor_sync(0xffffffffu, l0, 2);
    l1 += __shfl_xor_sync(0xffffffffu, l1, 1);
    l1 += __shfl_xor_sync(0xffffffffu, l1, 2);
    const float il0 = 1.0f / l0;
    const float il1 = 1.0f / l1;

    {
        const size_t rowA = (size_t)(b * SS + q0 + 16 * w + g) * DD + h * DK;
        const size_t rowB = (size_t)(b * SS + q0 + 16 * w + g + 8) * DD + h * DK;
#pragma unroll
        for (int ni = 0; ni < 8; ++ni) {
            const int col = ni * 8 + 2 * tig;
            __half2 hA, lA, hB, lB;
            split_h2(oacc[ni][0] * il0, oacc[ni][1] * il0, hA, lA);
            split_h2(oacc[ni][2] * il1, oacc[ni][3] * il1, hB, lB);
            *(__half2*)&g_CH[rowA + col] = hA;
            *(__half2*)&g_CL[rowA + col] = lA;
            *(__half2*)&g_CH[rowB + col] = hB;
            *(__half2*)&g_CL[rowB + col] = lB;
        }
    }

    __syncthreads();

    // ---- colsum readback ----
    for (int tile = 0; tile < 32; ++tile) {
        const uint4* U4 = (const uint4*)g_U + ((size_t)(blk * 32 + tile) * 4) * 256 + t;
        uint32_t uu[16];
        *(uint4*)&uu[0]  = U4[0];
        *(uint4*)&uu[4]  = U4[256];
        *(uint4*)&uu[8]  = U4[512];
        *(uint4*)&uu[12] = U4[768];
        const float w0 = __expf(mhist[tile * 128 + 16 * w + g]     - m0) * il0;
        const float w1 = __expf(mhist[tile * 128 + 16 * w + g + 8] - m1) * il1;

#pragma unroll
        for (int ni = 0; ni < 8; ++ni) {
            float2 fa = __half22float2(*(__half2*)&uu[2 * ni]);
            float2 fb = __half22float2(*(__half2*)&uu[2 * ni + 1]);
            float cs0 = fa.x * w0 + fb.x * w1;
            float cs1 = fa.y * w0 + fb.y * w1;
            cs0 += __shfl_xor_sync(0xffffffffu, cs0, 4);
            cs0 += __shfl_xor_sync(0xffffffffu, cs0, 8);
            cs0 += __shfl_xor_sync(0xffffffffu, cs0, 16);
            cs1 += __shfl_xor_sync(0xffffffffu, cs1, 4);
            cs1 += __shfl_xor_sync(0xffffffffu, cs1, 8);
            cs1 += __shfl_xor_sync(0xffffffffu, cs1, 16);
            if (lane < 4) {
                red[w * 64 + ni * 8 + 2 * tig]     = cs0;
                red[w * 64 + ni * 8 + 2 * tig + 1] = cs1;
            }
        }
        __syncthreads();
        if (t < 64) {
            float s = 0.0f;
#pragma unroll
            for (int wi = 0; wi < 8; ++wi) s += red[wi * 64 + t];
            atomicAdd(&atp[b * SS + tile * 64 + t], s * INV_HS);
        }
        __syncthreads();
    }
}

// ---------------- launch ------------------------------------------------------
extern "C" void kernel_launch(void* const* d_in, const int* in_sizes, int n_in,
                              void* d_out, int out_size) {
    (void)in_sizes; (void)n_in; (void)out_size;
    const float* query = (const float*)d_in[0];
    const float* key   = (const float*)d_in[1];
    const float* value = (const float*)d_in[2];
    const float* Wq = (const float*)d_in[3];
    const float* bq = (const float*)d_in[4];
    const float* Wk = (const float*)d_in[5];
    const float* bk = (const float*)d_in[6];
    const float* Wv = (const float*)d_in[7];
    const float* bv = (const float*)d_in[8];
    const float* Wo = (const float*)d_in[9];
    const float* bo = (const float*)d_in[10];

    float* out = (float*)d_out;
    float* atp = out + (size_t)BB * SS * DD;

    __half *inH, *inL, *QH, *QL, *KH, *KL, *VtH, *VtL, *CH, *CL;
    cudaGetSymbolAddress((void**)&inH, g_inH);
    cudaGetSymbolAddress((void**)&inL, g_inL);
    cudaGetSymbolAddress((void**)&QH, g_QH);
    cudaGetSymbolAddress((void**)&QL, g_QL);
    cudaGetSymbolAddress((void**)&KH, g_KH);
    cudaGetSymbolAddress((void**)&KL, g_KL);
    cudaGetSymbolAddress((void**)&VtH, g_VtH);
    cudaGetSymbolAddress((void**)&VtL, g_VtL);
    cudaGetSymbolAddress((void**)&CH, g_CH);
    cudaGetSymbolAddress((void**)&CL, g_CL);

    zero_atp_kernel<<<(BB*SS + 255) / 256, 256>>>(atp);

    const int NX4 = MTOT * DD / 4;
    const int NW4 = DD * DD / 4;
    const size_t oQ = 0, oK = 4194304, oV = 8388608;
    const size_t oWq = 12582912, oWk = 13631488, oWv = 14680064, oWo = 15728640;
    split_kernel<<<NX4 / 256, 256>>>(query, inH + oQ,  inL + oQ,  NX4);
    split_kernel<<<NX4 / 256, 256>>>(key,   inH + oK,  inL + oK,  NX4);
    split_kernel<<<NX4 / 256, 256>>>(value, inH + oV,  inL + oV,  NX4);
    split_kernel<<<NW4 / 256, 256>>>(Wq, inH + oWq, inL + oWq, NW4);
    split_kernel<<<NW4 / 256, 256>>>(Wk, inH + oWk, inL + oWk, NW4);
    split_kernel<<<NW4 / 256, 256>>>(Wv, inH + oWv, inL + oWv, NW4);
    split_kernel<<<NW4 / 256, 256>>>(Wo, inH + oWo, inL + oWo, NW4);

    cudaFuncSetAttribute(gemm_h16, cudaFuncAttributeMaxDynamicSharedMemorySize,
                         GEMM_SMEM);
    cudaFuncSetAttribute(attn_fused, cudaFuncAttributeMaxDynamicSharedMemorySize,
                         AT_SMEM);

    dim3 gg(GN / 128, MTOT / 128);
    gemm_h16<<<gg, 256, GEMM_SMEM>>>(inH + oQ, inL + oQ, inH + oWq, inL + oWq,
                                     bq, EP_H16, QH, QL, nullptr);
    gemm_h16<<<gg, 256, GEMM_SMEM>>>(inH + oK, inL + oK, inH + oWk, inL + oWk,
                                     bk, EP_H16, KH, KL, nullptr);
    gemm_h16<<<gg, 256, GEMM_SMEM>>>(inH + oV, inL + oV, inH + oWv, inL + oWv,
                                     bv, EP_VT, VtH, VtL, nullptr);

    attn_fused<<<dim3(16, 32), 256, AT_SMEM>>>(atp);

    gemm_h16<<<gg, 256, GEMM_SMEM>>>(CH, CL, inH + oWo, inL + oWo,
                                     bo, EP_F32, nullptr, nullptr, out);
}